// round 11
// baseline (speedup 1.0000x reference)
#include <cuda_runtime.h>
#include <cuda_bf16.h>
#include <cuda_fp16.h>
#include <math.h>
#include <stdint.h>

#define B_    2
#define T_    2048
#define DIM_  2048
#define NH_   16
#define NKV_  4
#define HD_   128
#define KD_   512
#define GQ_   (NH_ / NKV_)
#define EPS_  1.1920928955078125e-07f

// ---------------- scratch ----------------------------------------------------
__device__ float g_q[(size_t)B_ * T_ * DIM_];
__device__ float g_k[(size_t)B_ * T_ * KD_];
__device__ float g_cos[T_ * (HD_ / 2)];
__device__ float g_sin[T_ * (HD_ / 2)];
__device__ __half g_xhH[(size_t)B_ * T_ * DIM_];
__device__ __half g_xlH[(size_t)B_ * T_ * DIM_];
__device__ __half g_wqH[(size_t)DIM_ * DIM_];
__device__ __half g_wkH[(size_t)KD_ * DIM_];
__device__ __half g_wvH[(size_t)KD_ * DIM_];
__device__ __half g_wpH[(size_t)DIM_ * DIM_];
__device__ __half g_qH[(size_t)B_ * T_ * DIM_];
__device__ __half g_kH[(size_t)B_ * T_ * KD_];
__device__ __half g_vH[(size_t)B_ * T_ * KD_];
__device__ __half g_yH[(size_t)B_ * T_ * DIM_];

// ---------------- helpers ----------------------------------------------------
__device__ __forceinline__ uint32_t smem_u32(const void* p) {
    uint32_t a;
    asm("{ .reg .u64 t; cvta.to.shared.u64 t, %1; cvt.u32.u64 %0, t; }"
        : "=r"(a) : "l"(p));
    return a;
}
__device__ __forceinline__ void mma_f16(float* d, const uint32_t* a, const uint32_t* b) {
    asm volatile("mma.sync.aligned.m16n8k16.row.col.f32.f16.f16.f32 "
        "{%0,%1,%2,%3}, {%4,%5,%6,%7}, {%8,%9}, {%0,%1,%2,%3};"
        : "+f"(d[0]), "+f"(d[1]), "+f"(d[2]), "+f"(d[3])
        : "r"(a[0]), "r"(a[1]), "r"(a[2]), "r"(a[3]), "r"(b[0]), "r"(b[1]));
}
__device__ __forceinline__ void ldsm_x4(uint32_t* r, uint32_t addr) {
    asm volatile("ldmatrix.sync.aligned.m8n8.x4.shared.b16 {%0,%1,%2,%3}, [%4];"
        : "=r"(r[0]), "=r"(r[1]), "=r"(r[2]), "=r"(r[3]) : "r"(addr));
}
__device__ __forceinline__ void ldsm_x4_t(uint32_t* r, uint32_t addr) {
    asm volatile("ldmatrix.sync.aligned.m8n8.x4.trans.shared.b16 {%0,%1,%2,%3}, [%4];"
        : "=r"(r[0]), "=r"(r[1]), "=r"(r[2]), "=r"(r[3]) : "r"(addr));
}
__device__ __forceinline__ void cp16(uint32_t dst, const void* src) {
    asm volatile("cp.async.cg.shared.global [%0], [%1], 16;" :: "r"(dst), "l"(src));
}
#define CP_COMMIT() asm volatile("cp.async.commit_group;" ::: "memory")
#define CP_WAIT0()  asm volatile("cp.async.wait_group 0;" ::: "memory")
#define CP_WAIT1()  asm volatile("cp.async.wait_group 1;" ::: "memory")
#define CP_WAIT2()  asm volatile("cp.async.wait_group 2;" ::: "memory")

__device__ __forceinline__ void split4h(float4 f, uint2& hi, uint2& lo) {
    __half2 h0 = __floats2half2_rn(f.x, f.y);
    __half2 h1 = __floats2half2_rn(f.z, f.w);
    float2 g0 = __half22float2(h0), g1 = __half22float2(h1);
    __half2 l0 = __floats2half2_rn(f.x - g0.x, f.y - g0.y);
    __half2 l1 = __floats2half2_rn(f.z - g1.x, f.w - g1.y);
    hi.x = *(uint32_t*)&h0; hi.y = *(uint32_t*)&h1;
    lo.x = *(uint32_t*)&l0; lo.y = *(uint32_t*)&l1;
}
__device__ __forceinline__ uint2 tohalf4(float4 f) {
    __half2 h0 = __floats2half2_rn(f.x, f.y);
    __half2 h1 = __floats2half2_rn(f.z, f.w);
    return make_uint2(*(uint32_t*)&h0, *(uint32_t*)&h1);
}
#define NEG_INF __int_as_float(0xff800000)

// ---------------- RoPE tables ------------------------------------------------
__global__ void rope_table_kernel() {
    int idx = blockIdx.x * blockDim.x + threadIdx.x;
    if (idx >= T_ * (HD_ / 2)) return;
    int t = idx >> 6;
    int i = idx & 63;
    double base = 10000.0;
    if (T_ > 1024)
        base = 10000.0 * pow((double)T_ / 1024.0, (double)HD_ / (double)(HD_ - 2));
    double f = pow(base, -((double)(2 * i)) / (double)HD_);
    double a = (double)t * f;
    g_cos[idx] = (float)cos(a);
    g_sin[idx] = (float)sin(a);
}

// ---------------- fused operand prep ------------------------------------------
#define S_X   (B_ * T_ * DIM_ / 4)
#define S_WQ  (DIM_ * DIM_ / 4)
#define S_WK  (KD_ * DIM_ / 4)
#define SPLIT_TOT (S_X + S_WQ + S_WK + S_WK + S_WQ)

__global__ void split_all_kernel(const float* __restrict__ x,
                                 const float* __restrict__ Wq,
                                 const float* __restrict__ Wk,
                                 const float* __restrict__ Wv,
                                 const float* __restrict__ Wp)
{
    int i = blockIdx.x * blockDim.x + threadIdx.x;
    if (i < S_X) {
        float4 f = ((const float4*)x)[i];
        uint2 h, l; split4h(f, h, l);
        ((uint2*)g_xhH)[i] = h;
        ((uint2*)g_xlH)[i] = l;
        return;
    }
    i -= S_X;
    if (i < S_WQ) { ((uint2*)g_wqH)[i] = tohalf4(((const float4*)Wq)[i]); return; }
    i -= S_WQ;
    if (i < S_WK) { ((uint2*)g_wkH)[i] = tohalf4(((const float4*)Wk)[i]); return; }
    i -= S_WK;
    if (i < S_WK) { ((uint2*)g_wvH)[i] = tohalf4(((const float4*)Wv)[i]); return; }
    i -= S_WK;
    ((uint2*)g_wpH)[i] = tohalf4(((const float4*)Wp)[i]);
}

// ---------------- RMSNorm + RoPE (+gain) -> fp16 ------------------------------
__global__ void norm_rope_kernel(const float* __restrict__ data,
                                 const float* __restrict__ gain, int nheads,
                                 float post_mul, __half* __restrict__ oh)
{
    int gw   = (blockIdx.x * blockDim.x + threadIdx.x) >> 5;
    int lane = threadIdx.x & 31;
    int h = gw % nheads;
    int t = (gw / nheads) % T_;

    float4 v = *(const float4*)(data + (size_t)gw * HD_ + lane * 4);
    float ss = v.x * v.x + v.y * v.y + v.z * v.z + v.w * v.w;
    #pragma unroll
    for (int off = 16; off; off >>= 1)
        ss += __shfl_xor_sync(0xffffffffu, ss, off);
    float r = rsqrtf(ss * (1.f / HD_) + EPS_);

    float x[4] = { v.x * r, v.y * r, v.z * r, v.w * r };
    bool hi = lane >= 16;
    float g = (gain ? gain[h] : 1.f) * post_mul;

    float out[4];
    #pragma unroll
    for (int j = 0; j < 4; ++j) {
        float p = __shfl_xor_sync(0xffffffffu, x[j], 16);
        int i   = (lane & 15) * 4 + j;
        float c = g_cos[t * 64 + i];
        float s = g_sin[t * 64 + i];
        out[j] = (hi ? (x[j] * c - p * s) : (x[j] * c + p * s)) * g;
    }
    __half2 h0 = __floats2half2_rn(out[0], out[1]);
    __half2 h1 = __floats2half2_rn(out[2], out[3]);
    *(uint2*)(oh + (size_t)gw * HD_ + lane * 4) =
        make_uint2(*(uint32_t*)&h0, *(uint32_t*)&h1);
}

// ---------------- 2-term fp16 GEMM (fused Q+K projection) ----------------------
// C = xh*W + xl*W. CTA 128x256, BK=64, 256 thr (8 warps 2m x 4n, 64x64 warp
// tile), 3-stage cp.async. grid.x: 0..7 -> Q (bn=bx*256), 8..9 -> K.
#define TST      144
#define TPA      (128 * TST)                 // 18432 per A part
#define TPB      (256 * TST)                 // 36864 B part
#define TSTAGE2  (2 * TPA + TPB)             // 73728
#define TSMEM2   (3 * TSTAGE2)               // 221184

__global__ void __launch_bounds__(256, 1) gemm_qk2(
    const __half* __restrict__ Axh, const __half* __restrict__ Axl,
    const __half* __restrict__ Wq, const __half* __restrict__ Wk,
    float* __restrict__ Cq, float* __restrict__ Ck)
{
    extern __shared__ char sm[];
    const uint32_t sb = smem_u32(sm);
    const int tid = threadIdx.x, wid = tid >> 5, lane = tid & 31;
    const int wm = wid & 1, wn = wid >> 1;        // 2m x 4n, 64x64 tiles
    const int bm = blockIdx.y * 128;
    const int K = DIM_;

    const bool isQ = blockIdx.x < 8;
    const __half* W = isQ ? Wq : Wk;
    float* C = isQ ? Cq : Ck;
    const int N  = isQ ? DIM_ : KD_;
    const int bn = (isQ ? blockIdx.x : (blockIdx.x - 8)) * 256;

    float acc[4][8][4];
    #pragma unroll
    for (int i = 0; i < 4; ++i)
        #pragma unroll
        for (int j = 0; j < 8; ++j)
            #pragma unroll
            for (int q = 0; q < 4; ++q) acc[i][j][q] = 0.f;

    const int niter = K / 64;    // 32

    auto load_stage = [&](int it, int buf) {
        const int k0 = it * 64;
        const uint32_t s = sb + buf * TSTAGE2;
        #pragma unroll
        for (int p = 0; p < 16; ++p) {
            int idx = tid + p * 256;            // 0..4095
            if (idx < 2048) {                   // A hi/lo: 128 rows x 8 chunks
                int part = idx >> 10;           // 0=Ah 1=Al
                int r = (idx >> 3) & 127;
                int c = idx & 7;
                const __half* src = part ? Axl : Axh;
                cp16(s + part * TPA + r * TST + c * 16,
                     src + (size_t)(bm + r) * K + k0 + c * 8);
            } else {                            // B: 256 rows x 8 chunks
                int j = idx - 2048;
                int r = j >> 3;
                int c = j & 7;
                cp16(s + 2 * TPA + r * TST + c * 16,
                     W + (size_t)(bn + r) * K + k0 + c * 8);
            }
        }
    };

    load_stage(0, 0); CP_COMMIT();
    load_stage(1, 1); CP_COMMIT();

    for (int it = 0; it < niter; ++it) {
        const int buf = it % 3;
        CP_WAIT1();
        __syncthreads();
        if (it + 2 < niter) { load_stage(it + 2, (it + 2) % 3); CP_COMMIT(); }

        const uint32_t sbuf = sb + buf * TSTAGE2;
        #pragma unroll
        for (int ks = 0; ks < 4; ++ks) {
            uint32_t b[4][4];
            #pragma unroll
            for (int pr = 0; pr < 4; ++pr) {
                uint32_t rb = sbuf + 2 * TPA
                            + (wn * 64 + pr * 16 + (lane & 7) + ((lane >> 4) << 3)) * TST
                            + ks * 32 + (((lane >> 3) & 1) << 4);
                ldsm_x4(b[pr], rb);
            }
            #pragma unroll
            for (int mt = 0; mt < 4; ++mt) {
                uint32_t ah[4], al[4];
                uint32_t ra = sbuf + (wm * 64 + mt * 16 + (lane & 15)) * TST
                            + ks * 32 + ((lane >> 4) << 4);
                ldsm_x4(ah, ra);
                ldsm_x4(al, ra + TPA);
                #pragma unroll
                for (int nt = 0; nt < 8; ++nt) {
                    const uint32_t* bp = b[nt >> 1] + (nt & 1) * 2;
                    mma_f16(acc[mt][nt], ah, bp);
                    mma_f16(acc[mt][nt], al, bp);
                }
            }
        }
        __syncthreads();
    }

    #pragma unroll
    for (int mt = 0; mt < 4; ++mt)
        #pragma unroll
        for (int nt = 0; nt < 8; ++nt) {
            int row = bm + wm * 64 + mt * 16 + (lane >> 2);
            int col = bn + wn * 64 + nt * 8 + 2 * (lane & 3);
            *(float2*)(C + (size_t)row * N + col) =
                make_float2(acc[mt][nt][0], acc[mt][nt][1]);
            *(float2*)(C + (size_t)(row + 8) * N + col) =
                make_float2(acc[mt][nt][2], acc[mt][nt][3]);
        }
}

// ---------------- 1-term fp16 GEMM, CTA 128x256 (out projection) ---------------
#define OPA      (128 * TST)                 // 18432
#define OPB      (256 * TST)                 // 36864
#define OSTAGE   (OPA + OPB)                 // 55296
#define OSMEM    (4 * OSTAGE)                // 221184, 4 stages

__global__ void __launch_bounds__(256, 1) gemm_big(
    const __half* __restrict__ A, const __half* __restrict__ B,
    float* __restrict__ C, int N, int K)
{
    extern __shared__ char sm[];
    const uint32_t sb = smem_u32(sm);
    const int tid = threadIdx.x, wid = tid >> 5, lane = tid & 31;
    const int wm = wid & 1, wn = wid >> 1;
    const int bm = blockIdx.y * 128, bn = blockIdx.x * 256;

    float acc[4][8][4];
    #pragma unroll
    for (int i = 0; i < 4; ++i)
        #pragma unroll
        for (int j = 0; j < 8; ++j)
            #pragma unroll
            for (int q = 0; q < 4; ++q) acc[i][j][q] = 0.f;

    const int niter = K / 64;

    auto load_stage = [&](int it, int buf) {
        const int k0 = it * 64;
        const uint32_t s = sb + buf * OSTAGE;
        #pragma unroll
        for (int p = 0; p < 12; ++p) {
            int idx = tid + p * 256;            // 0..3071
            if (idx < 1024) {                   // A: 128 rows x 8 chunks
                int r = idx >> 3, c = idx & 7;
                cp16(s + r * TST + c * 16,
                     A + (size_t)(bm + r) * K + k0 + c * 8);
            } else {                            // B: 256 rows x 8 chunks
                int j = idx - 1024;
                int r = j >> 3, c = j & 7;
                cp16(s + OPA + r * TST + c * 16,
                     B + (size_t)(bn + r) * K + k0 + c * 8);
            }
        }
    };

    load_stage(0, 0); CP_COMMIT();
    load_stage(1, 1); CP_COMMIT();
    load_stage(2, 2); CP_COMMIT();

    for (int it = 0; it < niter; ++it) {
        const int buf = it & 3;
        CP_WAIT2();
        __syncthreads();
        if (it + 3 < niter) { load_stage(it + 3, (it + 3) & 3); CP_COMMIT(); }

        const uint32_t sbuf = sb + buf * OSTAGE;
        #pragma unroll
        for (int ks = 0; ks < 4; ++ks) {
            uint32_t b[4][4];
            #pragma unroll
            for (int pr = 0; pr < 4; ++pr) {
                uint32_t rb = sbuf + OPA
                            + (wn * 64 + pr * 16 + (lane & 7) + ((lane >> 4) << 3)) * TST
                            + ks * 32 + (((lane >> 3) & 1) << 4);
                ldsm_x4(b[pr], rb);
            }
            #pragma unroll
            for (int mt = 0; mt < 4; ++mt) {
                uint32_t a[4];
                uint32_t ra = sbuf + (wm * 64 + mt * 16 + (lane & 15)) * TST
                            + ks * 32 + ((lane >> 4) << 4);
                ldsm_x4(a, ra);
                #pragma unroll
                for (int nt = 0; nt < 8; ++nt)
                    mma_f16(acc[mt][nt], a, b[nt >> 1] + (nt & 1) * 2);
            }
        }
        __syncthreads();
    }

    #pragma unroll
    for (int mt = 0; mt < 4; ++mt)
        #pragma unroll
        for (int nt = 0; nt < 8; ++nt) {
            int row = bm + wm * 64 + mt * 16 + (lane >> 2);
            int col = bn + wn * 64 + nt * 8 + 2 * (lane & 3);
            *(float2*)(C + (size_t)row * N + col) =
                make_float2(acc[mt][nt][0], acc[mt][nt][1]);
            *(float2*)(C + (size_t)(row + 8) * N + col) =
                make_float2(acc[mt][nt][2], acc[mt][nt][3]);
        }
}

// ---------------- 1-term fp16 GEMM (V projection), 512 thr, 4-stage ------------
#define HST     144
#define HPART   (128 * HST)
#define HSTAGE  (2 * HPART)
#define HSMEM   (4 * HSTAGE)

__global__ void __launch_bounds__(512, 1) gemm_f16(
    const __half* __restrict__ A, const __half* __restrict__ B,
    __half* __restrict__ Ch, int N, int K)
{
    extern __shared__ char sm[];
    const uint32_t sb = smem_u32(sm);
    const int tid = threadIdx.x, wid = tid >> 5, lane = tid & 31;
    const int wm = wid & 3, wn = wid >> 2;
    const int bm = blockIdx.y * 128, bn = blockIdx.x * 128;

    float acc[2][4][4];
    #pragma unroll
    for (int i = 0; i < 2; ++i)
        #pragma unroll
        for (int j = 0; j < 4; ++j)
            #pragma unroll
            for (int q = 0; q < 4; ++q) acc[i][j][q] = 0.f;

    const int niter = K / 64;

    auto load_stage = [&](int it, int buf) {
        const int k0 = it * 64;
        const uint32_t s = sb + buf * HSTAGE;
        #pragma unroll
        for (int p = 0; p < 4; ++p) {
            int idx  = tid + p * 512;
            int part = idx >> 10;
            int r    = (idx >> 3) & 127;
            int c    = idx & 7;
            const __half* src = part ? B : A;
            int rowg = (part ? bn : bm) + r;
            cp16(s + part * HPART + r * HST + c * 16,
                 src + (size_t)rowg * K + k0 + c * 8);
        }
    };

    load_stage(0, 0); CP_COMMIT();
    load_stage(1, 1); CP_COMMIT();
    load_stage(2, 2); CP_COMMIT();

    for (int it = 0; it < niter; ++it) {
        const int buf = it & 3;
        CP_WAIT2();
        __syncthreads();
        if (it + 3 < niter) { load_stage(it + 3, (it + 3) & 3); CP_COMMIT(); }

        const uint32_t sbuf = sb + buf * HSTAGE;
        #pragma unroll
        for (int ks = 0; ks < 4; ++ks) {
            uint32_t a[2][4], b[2][4];
            #pragma unroll
            for (int mt = 0; mt < 2; ++mt) {
                uint32_t ra = sbuf + (wm * 32 + mt * 16 + (lane & 15)) * HST
                            + ks * 32 + ((lane >> 4) << 4);
                ldsm_x4(a[mt], ra);
            }
            #pragma unroll
            for (int pr = 0; pr < 2; ++pr) {
                uint32_t rb = sbuf + HPART
                            + (wn * 32 + pr * 16 + (lane & 7) + ((lane >> 4) << 3)) * HST
                            + ks * 32 + (((lane >> 3) & 1) << 4);
                ldsm_x4(b[pr], rb);
            }
            #pragma unroll
            for (int mt = 0; mt < 2; ++mt)
                #pragma unroll
                for (int nt = 0; nt < 4; ++nt)
                    mma_f16(acc[mt][nt], a[mt], b[nt >> 1] + (nt & 1) * 2);
        }
        __syncthreads();
    }

    #pragma unroll
    for (int mt = 0; mt < 2; ++mt)
        #pragma unroll
        for (int nt = 0; nt < 4; ++nt) {
            int row = bm + wm * 32 + mt * 16 + (lane >> 2);
            int col = bn + wn * 32 + nt * 8 + 2 * (lane & 3);
            __half2 u0 = __floats2half2_rn(acc[mt][nt][0], acc[mt][nt][1]);
            __half2 u1 = __floats2half2_rn(acc[mt][nt][2], acc[mt][nt][3]);
            *(uint32_t*)(Ch + (size_t)row * N + col)       = *(uint32_t*)&u0;
            *(uint32_t*)(Ch + (size_t)(row + 8) * N + col) = *(uint32_t*)&u1;
        }
}

// ---------------- flash attention: 1-term fp16, Q in registers ----------------
#define FST    272
#define QT     (128 * FST)
#define KVP    (64 * FST)
#define STG    (2 * KVP)
#define FSMEM  (QT + 2 * STG)

__global__ void __launch_bounds__(256, 1) flash_mma(
    const __half* __restrict__ qH, const __half* __restrict__ kH,
    const __half* __restrict__ vH, __half* __restrict__ y)
{
    extern __shared__ char sm[];
    const uint32_t sb = smem_u32(sm);
    const int tid = threadIdx.x, wid = tid >> 5, lane = tid & 31;
    const int itq = (gridDim.x - 1) - blockIdx.x;
    const int h = blockIdx.y, b = blockIdx.z;
    const int kvh = h / GQ_;
    const int t0q = itq * 128;
    const int jmax = 2 * itq + 1;

    #pragma unroll
    for (int p = 0; p < 8; ++p) {
        int idx = tid + p * 256;
        int r = (idx >> 4) & 127, c = idx & 15;
        cp16(sb + r * FST + c * 16,
             qH + ((size_t)(b * T_ + t0q + r) * NH_ + h) * HD_ + c * 8);
    }
    #pragma unroll
    for (int p = 0; p < 8; ++p) {
        int idx = tid + p * 256;
        int part = idx >> 10;
        int r = (idx >> 4) & 63, c = idx & 15;
        const __half* src = part ? vH : kH;
        cp16(sb + QT + part * KVP + r * FST + c * 16,
             src + ((size_t)(b * T_ + r) * NKV_ + kvh) * HD_ + c * 8);
    }
    CP_COMMIT();
    CP_WAIT0();
    __syncthreads();

    uint32_t QF[8][4];
    #pragma unroll
    for (int ks = 0; ks < 8; ++ks) {
        uint32_t ra = sb + (wid * 16 + (lane & 15)) * FST
                    + ks * 32 + ((lane >> 4) << 4);
        ldsm_x4(QF[ks], ra);
    }

    float m0 = NEG_INF, m1 = NEG_INF, l0 = 0.f, l1 = 0.f;
    float O[16][4];
    #pragma unroll
    for (int nt = 0; nt < 16; ++nt)
        #pragma unroll
        for (int j = 0; j < 4; ++j) O[nt][j] = 0.f;

    const int row_a = t0q + wid * 16 + (lane >> 2);

    for (int jt = 0; jt <= jmax; ++jt) {
        const int buf = jt & 1;
        if (jt > 0) { CP_WAIT0(); __syncthreads(); }
        if (jt + 1 <= jmax) {
            const int t0n = (jt + 1) * 64;
            #pragma unroll
            for (int p = 0; p < 8; ++p) {
                int idx = tid + p * 256;
                int part = idx >> 10;
                int r = (idx >> 4) & 63, c = idx & 15;
                const __half* src = part ? vH : kH;
                cp16(sb + QT + (buf ^ 1) * STG + part * KVP + r * FST + c * 16,
                     src + ((size_t)(b * T_ + t0n + r) * NKV_ + kvh) * HD_ + c * 8);
            }
            CP_COMMIT();
        }

        const uint32_t base_k = sb + QT + buf * STG;
        const int t0k = jt * 64;

        float S[8][4];
        #pragma unroll
        for (int nt = 0; nt < 8; ++nt)
            #pragma unroll
            for (int j = 0; j < 4; ++j) S[nt][j] = 0.f;

        #pragma unroll
        for (int ks = 0; ks < 8; ++ks) {
            #pragma unroll
            for (int ntp = 0; ntp < 4; ++ntp) {
                uint32_t bh[4];
                uint32_t rb = base_k
                            + (ntp * 16 + (lane & 7) + ((lane >> 4) << 3)) * FST
                            + ks * 32 + (((lane >> 3) & 1) << 4);
                ldsm_x4(bh, rb);
                mma_f16(S[2 * ntp],     QF[ks], bh);
                mma_f16(S[2 * ntp + 1], QF[ks], bh + 2);
            }
        }

        const bool diag = (jt >= 2 * itq);
        float ml0 = NEG_INF, ml1 = NEG_INF;
        #pragma unroll
        for (int nt = 0; nt < 8; ++nt) {
            int c = t0k + nt * 8 + 2 * (lane & 3);
            if (diag) {
                if (c     > row_a)     S[nt][0] = NEG_INF;
                if (c + 1 > row_a)     S[nt][1] = NEG_INF;
                if (c     > row_a + 8) S[nt][2] = NEG_INF;
                if (c + 1 > row_a + 8) S[nt][3] = NEG_INF;
            }
            ml0 = fmaxf(ml0, fmaxf(S[nt][0], S[nt][1]));
            ml1 = fmaxf(ml1, fmaxf(S[nt][2], S[nt][3]));
        }
        ml0 = fmaxf(ml0, __shfl_xor_sync(0xffffffffu, ml0, 1));
        ml0 = fmaxf(ml0, __shfl_xor_sync(0xffffffffu, ml0, 2));
        ml1 = fmaxf(ml1, __shfl_xor_sync(0xffffffffu, ml1, 1));
        ml1 = fmaxf(ml1, __shfl_xor_sync(0xffffffffu, ml1, 2));

        float mn0 = fmaxf(m0, ml0), mn1 = fmaxf(m1, ml1);
        float es0 = exp2f(m0 - mn0);
        float es1 = exp2f(m1 - mn1);
        m0 = mn0; m1 = mn1;

        float sum0 = 0.f, sum1 = 0.f;
        uint32_t PH[16];
        #pragma unroll
        for (int nt = 0; nt < 8; ++nt) {
            float p0 = exp2f(S[nt][0] - mn0);
            float p1 = exp2f(S[nt][1] - mn0);
            float p2 = exp2f(S[nt][2] - mn1);
            float p3 = exp2f(S[nt][3] - mn1);
            sum0 += p0 + p1;  sum1 += p2 + p3;
            __half2 hA = __floats2half2_rn(p0, p1);
            __half2 hB = __floats2half2_rn(p2, p3);
            PH[2 * nt]     = *(uint32_t*)&hA;
            PH[2 * nt + 1] = *(uint32_t*)&hB;
        }
        sum0 += __shfl_xor_sync(0xffffffffu, sum0, 1);
        sum0 += __shfl_xor_sync(0xffffffffu, sum0, 2);
        sum1 += __shfl_xor_sync(0xffffffffu, sum1, 1);
        sum1 += __shfl_xor_sync(0xffffffffu, sum1, 2);
        l0 = l0 * es0 + sum0;
        l1 = l1 * es1 + sum1;
        #pragma unroll
        for (int nt = 0; nt < 16; ++nt) {
            O[nt][0] *= es0; O[nt][1] *= es0;
            O[nt][2] *= es1; O[nt][3] *= es1;
        }

        const uint32_t base_v = base_k + KVP;
        #pragma unroll
        for (int kt = 0; kt < 4; ++kt) {
            uint32_t pa[4] = { PH[4*kt], PH[4*kt+1], PH[4*kt+2], PH[4*kt+3] };
            #pragma unroll
            for (int ntp = 0; ntp < 8; ++ntp) {
                uint32_t bh[4];
                uint32_t rv = base_v
                            + (kt * 16 + (lane & 7) + (lane & 8)) * FST
                            + ntp * 32 + ((lane >> 4) << 4);
                ldsm_x4_t(bh, rv);
                mma_f16(O[2 * ntp],     pa, bh);
                mma_f16(O[2 * ntp + 1], pa, bh + 2);
            }
        }
    }

    float inv0 = 1.f / l0, inv1 = 1.f / l1;
    #pragma unroll
    for (int nt = 0; nt < 16; ++nt) {
        int c = nt * 8 + 2 * (lane & 3);
        size_t baseA = ((size_t)(b * T_ + row_a) * NH_ + h) * HD_ + c;
        size_t baseB = ((size_t)(b * T_ + row_a + 8) * NH_ + h) * HD_ + c;
        __half2 uA = __floats2half2_rn(O[nt][0] * inv0, O[nt][1] * inv0);
        __half2 uB = __floats2half2_rn(O[nt][2] * inv1, O[nt][3] * inv1);
        *(uint32_t*)(y + baseA) = *(uint32_t*)&uA;
        *(uint32_t*)(y + baseB) = *(uint32_t*)&uB;
    }
}

// ---------------------------------------------------------------------------
extern "C" void kernel_launch(void* const* d_in, const int* in_sizes, int n_in,
                              void* d_out, int out_size)
{
    const float* x  = (const float*)d_in[0];
    const float* Wq = (const float*)d_in[1];
    const float* Wk = (const float*)d_in[2];
    const float* Wv = (const float*)d_in[3];
    const float* Wp = (const float*)d_in[4];
    const float* qg = (const float*)d_in[5];
    float* out = (float*)d_out;

    float *q, *kk;
    cudaGetSymbolAddress((void**)&q,  g_q);
    cudaGetSymbolAddress((void**)&kk, g_k);
    __half *xhH, *xlH, *wqH, *wkH, *wvH, *wpH, *qh16, *kh16, *vh16, *yH;
    cudaGetSymbolAddress((void**)&xhH, g_xhH);
    cudaGetSymbolAddress((void**)&xlH, g_xlH);
    cudaGetSymbolAddress((void**)&wqH, g_wqH);
    cudaGetSymbolAddress((void**)&wkH, g_wkH);
    cudaGetSymbolAddress((void**)&wvH, g_wvH);
    cudaGetSymbolAddress((void**)&wpH, g_wpH);
    cudaGetSymbolAddress((void**)&qh16, g_qH);
    cudaGetSymbolAddress((void**)&kh16, g_kH);
    cudaGetSymbolAddress((void**)&vh16, g_vH);
    cudaGetSymbolAddress((void**)&yH,  g_yH);

    cudaFuncSetAttribute(gemm_qk2, cudaFuncAttributeMaxDynamicSharedMemorySize, TSMEM2);
    cudaFuncSetAttribute(gemm_big, cudaFuncAttributeMaxDynamicSharedMemorySize, OSMEM);
    cudaFuncSetAttribute(gemm_f16, cudaFuncAttributeMaxDynamicSharedMemorySize, HSMEM);
    cudaFuncSetAttribute(flash_mma, cudaFuncAttributeMaxDynamicSharedMemorySize, FSMEM);

    // (0) RoPE tables, (1) operand prep
    rope_table_kernel<<<(T_ * 64 + 255) / 256, 256>>>();
    split_all_kernel<<<SPLIT_TOT / 256, 256>>>(x, Wq, Wk, Wv, Wp);

    // (2) fused Q+K projection (2-term fp16, 64x64 warp tiles)
    gemm_qk2<<<dim3(10, (B_ * T_) / 128), 256, TSMEM2>>>(
        xhH, xlH, wqH, wkH, q, kk);

    // (3) V proj (fp16 1-term) -> vH
    dim3 gk(KD_ / 128, (B_ * T_) / 128);
    gemm_f16<<<gk, 512, HSMEM>>>(xhH, wvH, vh16, KD_, DIM_);

    // (4,5) RMSNorm + RoPE -> fp16
    const float QMUL = 0.08838834764831845f * 1.44269504088896340736f;
    norm_rope_kernel<<<(B_ * T_ * NH_  * 32) / 256, 256>>>(q,  qg,      NH_,  QMUL, qh16);
    norm_rope_kernel<<<(B_ * T_ * NKV_ * 32) / 256, 256>>>(kk, nullptr, NKV_, 1.0f, kh16);

    // (6) flash attention -> y fp16
    flash_mma<<<dim3(T_ / 128, NH_, B_), 256, FSMEM>>>(qh16, kh16, vh16, yH);

    // (7) out proj (fp16 1-term, 64x64 warp tiles) -> fp32 out
    gemm_big<<<dim3(DIM_ / 256, (B_ * T_) / 128), 256, OSMEM>>>(
        yH, wpH, out, DIM_, DIM_);
}

// round 12
// speedup vs baseline: 1.1588x; 1.1588x over previous
#include <cuda_runtime.h>
#include <cuda_bf16.h>
#include <cuda_fp16.h>
#include <math.h>
#include <stdint.h>

#define B_    2
#define T_    2048
#define DIM_  2048
#define NH_   16
#define NKV_  4
#define HD_   128
#define KD_   512
#define GQ_   (NH_ / NKV_)
#define EPS_  1.1920928955078125e-07f

// ---------------- scratch ----------------------------------------------------
__device__ float g_q[(size_t)B_ * T_ * DIM_];
__device__ float g_k[(size_t)B_ * T_ * KD_];
__device__ float g_cos[T_ * (HD_ / 2)];
__device__ float g_sin[T_ * (HD_ / 2)];
__device__ __half g_xH[(size_t)B_ * T_ * DIM_];
__device__ __half g_wqH[(size_t)DIM_ * DIM_];
__device__ __half g_wkH[(size_t)KD_ * DIM_];
__device__ __half g_wvH[(size_t)KD_ * DIM_];
__device__ __half g_wpH[(size_t)DIM_ * DIM_];
__device__ __half g_qH[(size_t)B_ * T_ * DIM_];
__device__ __half g_kH[(size_t)B_ * T_ * KD_];
__device__ __half g_vH[(size_t)B_ * T_ * KD_];
__device__ __half g_yH[(size_t)B_ * T_ * DIM_];

// ---------------- helpers ----------------------------------------------------
__device__ __forceinline__ uint32_t smem_u32(const void* p) {
    uint32_t a;
    asm("{ .reg .u64 t; cvta.to.shared.u64 t, %1; cvt.u32.u64 %0, t; }"
        : "=r"(a) : "l"(p));
    return a;
}
__device__ __forceinline__ void mma_f16(float* d, const uint32_t* a, const uint32_t* b) {
    asm volatile("mma.sync.aligned.m16n8k16.row.col.f32.f16.f16.f32 "
        "{%0,%1,%2,%3}, {%4,%5,%6,%7}, {%8,%9}, {%0,%1,%2,%3};"
        : "+f"(d[0]), "+f"(d[1]), "+f"(d[2]), "+f"(d[3])
        : "r"(a[0]), "r"(a[1]), "r"(a[2]), "r"(a[3]), "r"(b[0]), "r"(b[1]));
}
__device__ __forceinline__ void ldsm_x4(uint32_t* r, uint32_t addr) {
    asm volatile("ldmatrix.sync.aligned.m8n8.x4.shared.b16 {%0,%1,%2,%3}, [%4];"
        : "=r"(r[0]), "=r"(r[1]), "=r"(r[2]), "=r"(r[3]) : "r"(addr));
}
__device__ __forceinline__ void ldsm_x4_t(uint32_t* r, uint32_t addr) {
    asm volatile("ldmatrix.sync.aligned.m8n8.x4.trans.shared.b16 {%0,%1,%2,%3}, [%4];"
        : "=r"(r[0]), "=r"(r[1]), "=r"(r[2]), "=r"(r[3]) : "r"(addr));
}
__device__ __forceinline__ void cp16(uint32_t dst, const void* src) {
    asm volatile("cp.async.cg.shared.global [%0], [%1], 16;" :: "r"(dst), "l"(src));
}
#define CP_COMMIT() asm volatile("cp.async.commit_group;" ::: "memory")
#define CP_WAIT0()  asm volatile("cp.async.wait_group 0;" ::: "memory")
#define CP_WAIT2()  asm volatile("cp.async.wait_group 2;" ::: "memory")

__device__ __forceinline__ uint2 tohalf4(float4 f) {
    __half2 h0 = __floats2half2_rn(f.x, f.y);
    __half2 h1 = __floats2half2_rn(f.z, f.w);
    return make_uint2(*(uint32_t*)&h0, *(uint32_t*)&h1);
}
#define NEG_INF __int_as_float(0xff800000)

// ---------------- RoPE tables ------------------------------------------------
__global__ void rope_table_kernel() {
    int idx = blockIdx.x * blockDim.x + threadIdx.x;
    if (idx >= T_ * (HD_ / 2)) return;
    int t = idx >> 6;
    int i = idx & 63;
    double base = 10000.0;
    if (T_ > 1024)
        base = 10000.0 * pow((double)T_ / 1024.0, (double)HD_ / (double)(HD_ - 2));
    double f = pow(base, -((double)(2 * i)) / (double)HD_);
    double a = (double)t * f;
    g_cos[idx] = (float)cos(a);
    g_sin[idx] = (float)sin(a);
}

// ---------------- operand prep: fp32 -> fp16 ----------------------------------
#define S_X   (B_ * T_ * DIM_ / 4)
#define S_WQ  (DIM_ * DIM_ / 4)
#define S_WK  (KD_ * DIM_ / 4)
#define SPLIT_TOT (S_X + S_WQ + S_WK + S_WK + S_WQ)

__global__ void split_all_kernel(const float* __restrict__ x,
                                 const float* __restrict__ Wq,
                                 const float* __restrict__ Wk,
                                 const float* __restrict__ Wv,
                                 const float* __restrict__ Wp)
{
    int i = blockIdx.x * blockDim.x + threadIdx.x;
    if (i < S_X)  { ((uint2*)g_xH)[i]  = tohalf4(((const float4*)x)[i]);  return; }
    i -= S_X;
    if (i < S_WQ) { ((uint2*)g_wqH)[i] = tohalf4(((const float4*)Wq)[i]); return; }
    i -= S_WQ;
    if (i < S_WK) { ((uint2*)g_wkH)[i] = tohalf4(((const float4*)Wk)[i]); return; }
    i -= S_WK;
    if (i < S_WK) { ((uint2*)g_wvH)[i] = tohalf4(((const float4*)Wv)[i]); return; }
    i -= S_WK;
    ((uint2*)g_wpH)[i] = tohalf4(((const float4*)Wp)[i]);
}

// ---------------- RMSNorm + RoPE (+gain) -> fp16 ------------------------------
__global__ void norm_rope_kernel(const float* __restrict__ data,
                                 const float* __restrict__ gain, int nheads,
                                 float post_mul, __half* __restrict__ oh)
{
    int gw   = (blockIdx.x * blockDim.x + threadIdx.x) >> 5;
    int lane = threadIdx.x & 31;
    int h = gw % nheads;
    int t = (gw / nheads) % T_;

    float4 v = *(const float4*)(data + (size_t)gw * HD_ + lane * 4);
    float ss = v.x * v.x + v.y * v.y + v.z * v.z + v.w * v.w;
    #pragma unroll
    for (int off = 16; off; off >>= 1)
        ss += __shfl_xor_sync(0xffffffffu, ss, off);
    float r = rsqrtf(ss * (1.f / HD_) + EPS_);

    float x[4] = { v.x * r, v.y * r, v.z * r, v.w * r };
    bool hi = lane >= 16;
    float g = (gain ? gain[h] : 1.f) * post_mul;

    float out[4];
    #pragma unroll
    for (int j = 0; j < 4; ++j) {
        float p = __shfl_xor_sync(0xffffffffu, x[j], 16);
        int i   = (lane & 15) * 4 + j;
        float c = g_cos[t * 64 + i];
        float s = g_sin[t * 64 + i];
        out[j] = (hi ? (x[j] * c - p * s) : (x[j] * c + p * s)) * g;
    }
    __half2 h0 = __floats2half2_rn(out[0], out[1]);
    __half2 h1 = __floats2half2_rn(out[2], out[3]);
    *(uint2*)(oh + (size_t)gw * HD_ + lane * 4) =
        make_uint2(*(uint32_t*)&h0, *(uint32_t*)&h1);
}

// ---------------- 1-term fp16 GEMM body (proven 512-thr shape) -----------------
#define HST     144
#define HPART   (128 * HST)
#define HSTAGE  (2 * HPART)
#define HSMEM   (4 * HSTAGE)

__device__ __forceinline__ void gemm1_body(
    const __half* __restrict__ A, const __half* __restrict__ W,
    float* __restrict__ C, __half* __restrict__ Ch,
    int N, int K, int bm, int bn)
{
    extern __shared__ char sm[];
    const uint32_t sb = smem_u32(sm);
    const int tid = threadIdx.x, wid = tid >> 5, lane = tid & 31;
    const int wm = wid & 3, wn = wid >> 2;

    float acc[2][4][4];
    #pragma unroll
    for (int i = 0; i < 2; ++i)
        #pragma unroll
        for (int j = 0; j < 4; ++j)
            #pragma unroll
            for (int q = 0; q < 4; ++q) acc[i][j][q] = 0.f;

    const int niter = K / 64;

    auto load_stage = [&](int it, int buf) {
        const int k0 = it * 64;
        const uint32_t s = sb + buf * HSTAGE;
        #pragma unroll
        for (int p = 0; p < 4; ++p) {
            int idx  = tid + p * 512;
            int part = idx >> 10;
            int r    = (idx >> 3) & 127;
            int c    = idx & 7;
            const __half* src = part ? W : A;
            int rowg = (part ? bn : bm) + r;
            cp16(s + part * HPART + r * HST + c * 16,
                 src + (size_t)rowg * K + k0 + c * 8);
        }
    };

    load_stage(0, 0); CP_COMMIT();
    load_stage(1, 1); CP_COMMIT();
    load_stage(2, 2); CP_COMMIT();

    for (int it = 0; it < niter; ++it) {
        const int buf = it & 3;
        CP_WAIT2();
        __syncthreads();
        if (it + 3 < niter) { load_stage(it + 3, (it + 3) & 3); CP_COMMIT(); }

        const uint32_t sbuf = sb + buf * HSTAGE;
        #pragma unroll
        for (int ks = 0; ks < 4; ++ks) {
            uint32_t a[2][4], b[2][4];
            #pragma unroll
            for (int mt = 0; mt < 2; ++mt) {
                uint32_t ra = sbuf + (wm * 32 + mt * 16 + (lane & 15)) * HST
                            + ks * 32 + ((lane >> 4) << 4);
                ldsm_x4(a[mt], ra);
            }
            #pragma unroll
            for (int pr = 0; pr < 2; ++pr) {
                uint32_t rb = sbuf + HPART
                            + (wn * 32 + pr * 16 + (lane & 7) + ((lane >> 4) << 3)) * HST
                            + ks * 32 + (((lane >> 3) & 1) << 4);
                ldsm_x4(b[pr], rb);
            }
            #pragma unroll
            for (int mt = 0; mt < 2; ++mt)
                #pragma unroll
                for (int nt = 0; nt < 4; ++nt)
                    mma_f16(acc[mt][nt], a[mt], b[nt >> 1] + (nt & 1) * 2);
        }
        __syncthreads();
    }

    #pragma unroll
    for (int mt = 0; mt < 2; ++mt)
        #pragma unroll
        for (int nt = 0; nt < 4; ++nt) {
            int row = bm + wm * 32 + mt * 16 + (lane >> 2);
            int col = bn + wn * 32 + nt * 8 + 2 * (lane & 3);
            if (Ch) {
                __half2 u0 = __floats2half2_rn(acc[mt][nt][0], acc[mt][nt][1]);
                __half2 u1 = __floats2half2_rn(acc[mt][nt][2], acc[mt][nt][3]);
                *(uint32_t*)(Ch + (size_t)row * N + col)       = *(uint32_t*)&u0;
                *(uint32_t*)(Ch + (size_t)(row + 8) * N + col) = *(uint32_t*)&u1;
            } else {
                *(float2*)(C + (size_t)row * N + col) =
                    make_float2(acc[mt][nt][0], acc[mt][nt][1]);
                *(float2*)(C + (size_t)(row + 8) * N + col) =
                    make_float2(acc[mt][nt][2], acc[mt][nt][3]);
            }
        }
}

// fused Q+K+V projection: one launch, tiles 0..15 -> Q, 16..19 -> K, 20..23 -> V
__global__ void __launch_bounds__(512, 1) gemm_qkv(
    const __half* __restrict__ xH,
    const __half* __restrict__ wq, const __half* __restrict__ wk,
    const __half* __restrict__ wv,
    float* __restrict__ Cq, float* __restrict__ Ck, __half* __restrict__ Cv)
{
    const int bx = blockIdx.x;
    if (bx < 16)
        gemm1_body(xH, wq, Cq, nullptr, DIM_, DIM_, blockIdx.y * 128, bx * 128);
    else if (bx < 20)
        gemm1_body(xH, wk, Ck, nullptr, KD_, DIM_, blockIdx.y * 128, (bx - 16) * 128);
    else
        gemm1_body(xH, wv, nullptr, Cv, KD_, DIM_, blockIdx.y * 128, (bx - 20) * 128);
}

// out projection
__global__ void __launch_bounds__(512, 1) gemm_out(
    const __half* __restrict__ A, const __half* __restrict__ W,
    float* __restrict__ C, int N, int K)
{
    gemm1_body(A, W, C, nullptr, N, K, blockIdx.y * 128, blockIdx.x * 128);
}

// ---------------- flash attention: 1-term fp16, Q in registers ----------------
#define FST    272
#define QT     (128 * FST)
#define KVP    (64 * FST)
#define STG    (2 * KVP)
#define FSMEM  (QT + 2 * STG)

__global__ void __launch_bounds__(256, 1) flash_mma(
    const __half* __restrict__ qH, const __half* __restrict__ kH,
    const __half* __restrict__ vH, __half* __restrict__ y)
{
    extern __shared__ char sm[];
    const uint32_t sb = smem_u32(sm);
    const int tid = threadIdx.x, wid = tid >> 5, lane = tid & 31;
    const int itq = (gridDim.x - 1) - blockIdx.x;
    const int h = blockIdx.y, b = blockIdx.z;
    const int kvh = h / GQ_;
    const int t0q = itq * 128;
    const int jmax = 2 * itq + 1;

    #pragma unroll
    for (int p = 0; p < 8; ++p) {
        int idx = tid + p * 256;
        int r = (idx >> 4) & 127, c = idx & 15;
        cp16(sb + r * FST + c * 16,
             qH + ((size_t)(b * T_ + t0q + r) * NH_ + h) * HD_ + c * 8);
    }
    #pragma unroll
    for (int p = 0; p < 8; ++p) {
        int idx = tid + p * 256;
        int part = idx >> 10;
        int r = (idx >> 4) & 63, c = idx & 15;
        const __half* src = part ? vH : kH;
        cp16(sb + QT + part * KVP + r * FST + c * 16,
             src + ((size_t)(b * T_ + r) * NKV_ + kvh) * HD_ + c * 8);
    }
    CP_COMMIT();
    CP_WAIT0();
    __syncthreads();

    uint32_t QF[8][4];
    #pragma unroll
    for (int ks = 0; ks < 8; ++ks) {
        uint32_t ra = sb + (wid * 16 + (lane & 15)) * FST
                    + ks * 32 + ((lane >> 4) << 4);
        ldsm_x4(QF[ks], ra);
    }

    float m0 = NEG_INF, m1 = NEG_INF, l0 = 0.f, l1 = 0.f;
    float O[16][4];
    #pragma unroll
    for (int nt = 0; nt < 16; ++nt)
        #pragma unroll
        for (int j = 0; j < 4; ++j) O[nt][j] = 0.f;

    const int row_a = t0q + wid * 16 + (lane >> 2);

    for (int jt = 0; jt <= jmax; ++jt) {
        const int buf = jt & 1;
        if (jt > 0) { CP_WAIT0(); __syncthreads(); }
        if (jt + 1 <= jmax) {
            const int t0n = (jt + 1) * 64;
            #pragma unroll
            for (int p = 0; p < 8; ++p) {
                int idx = tid + p * 256;
                int part = idx >> 10;
                int r = (idx >> 4) & 63, c = idx & 15;
                const __half* src = part ? vH : kH;
                cp16(sb + QT + (buf ^ 1) * STG + part * KVP + r * FST + c * 16,
                     src + ((size_t)(b * T_ + t0n + r) * NKV_ + kvh) * HD_ + c * 8);
            }
            CP_COMMIT();
        }

        const uint32_t base_k = sb + QT + buf * STG;
        const int t0k = jt * 64;

        float S[8][4];
        #pragma unroll
        for (int nt = 0; nt < 8; ++nt)
            #pragma unroll
            for (int j = 0; j < 4; ++j) S[nt][j] = 0.f;

        #pragma unroll
        for (int ks = 0; ks < 8; ++ks) {
            #pragma unroll
            for (int ntp = 0; ntp < 4; ++ntp) {
                uint32_t bh[4];
                uint32_t rb = base_k
                            + (ntp * 16 + (lane & 7) + ((lane >> 4) << 3)) * FST
                            + ks * 32 + (((lane >> 3) & 1) << 4);
                ldsm_x4(bh, rb);
                mma_f16(S[2 * ntp],     QF[ks], bh);
                mma_f16(S[2 * ntp + 1], QF[ks], bh + 2);
            }
        }

        const bool diag = (jt >= 2 * itq);
        float ml0 = NEG_INF, ml1 = NEG_INF;
        #pragma unroll
        for (int nt = 0; nt < 8; ++nt) {
            int c = t0k + nt * 8 + 2 * (lane & 3);
            if (diag) {
                if (c     > row_a)     S[nt][0] = NEG_INF;
                if (c + 1 > row_a)     S[nt][1] = NEG_INF;
                if (c     > row_a + 8) S[nt][2] = NEG_INF;
                if (c + 1 > row_a + 8) S[nt][3] = NEG_INF;
            }
            ml0 = fmaxf(ml0, fmaxf(S[nt][0], S[nt][1]));
            ml1 = fmaxf(ml1, fmaxf(S[nt][2], S[nt][3]));
        }
        ml0 = fmaxf(ml0, __shfl_xor_sync(0xffffffffu, ml0, 1));
        ml0 = fmaxf(ml0, __shfl_xor_sync(0xffffffffu, ml0, 2));
        ml1 = fmaxf(ml1, __shfl_xor_sync(0xffffffffu, ml1, 1));
        ml1 = fmaxf(ml1, __shfl_xor_sync(0xffffffffu, ml1, 2));

        float mn0 = fmaxf(m0, ml0), mn1 = fmaxf(m1, ml1);
        float es0 = exp2f(m0 - mn0);
        float es1 = exp2f(m1 - mn1);
        m0 = mn0; m1 = mn1;

        float sum0 = 0.f, sum1 = 0.f;
        uint32_t PH[16];
        #pragma unroll
        for (int nt = 0; nt < 8; ++nt) {
            float p0 = exp2f(S[nt][0] - mn0);
            float p1 = exp2f(S[nt][1] - mn0);
            float p2 = exp2f(S[nt][2] - mn1);
            float p3 = exp2f(S[nt][3] - mn1);
            sum0 += p0 + p1;  sum1 += p2 + p3;
            __half2 hA = __floats2half2_rn(p0, p1);
            __half2 hB = __floats2half2_rn(p2, p3);
            PH[2 * nt]     = *(uint32_t*)&hA;
            PH[2 * nt + 1] = *(uint32_t*)&hB;
        }
        sum0 += __shfl_xor_sync(0xffffffffu, sum0, 1);
        sum0 += __shfl_xor_sync(0xffffffffu, sum0, 2);
        sum1 += __shfl_xor_sync(0xffffffffu, sum1, 1);
        sum1 += __shfl_xor_sync(0xffffffffu, sum1, 2);
        l0 = l0 * es0 + sum0;
        l1 = l1 * es1 + sum1;
        #pragma unroll
        for (int nt = 0; nt < 16; ++nt) {
            O[nt][0] *= es0; O[nt][1] *= es0;
            O[nt][2] *= es1; O[nt][3] *= es1;
        }

        const uint32_t base_v = base_k + KVP;
        #pragma unroll
        for (int kt = 0; kt < 4; ++kt) {
            uint32_t pa[4] = { PH[4*kt], PH[4*kt+1], PH[4*kt+2], PH[4*kt+3] };
            #pragma unroll
            for (int ntp = 0; ntp < 8; ++ntp) {
                uint32_t bh[4];
                uint32_t rv = base_v
                            + (kt * 16 + (lane & 7) + (lane & 8)) * FST
                            + ntp * 32 + ((lane >> 4) << 4);
                ldsm_x4_t(bh, rv);
                mma_f16(O[2 * ntp],     pa, bh);
                mma_f16(O[2 * ntp + 1], pa, bh + 2);
            }
        }
    }

    float inv0 = 1.f / l0, inv1 = 1.f / l1;
    #pragma unroll
    for (int nt = 0; nt < 16; ++nt) {
        int c = nt * 8 + 2 * (lane & 3);
        size_t baseA = ((size_t)(b * T_ + row_a) * NH_ + h) * HD_ + c;
        size_t baseB = ((size_t)(b * T_ + row_a + 8) * NH_ + h) * HD_ + c;
        __half2 uA = __floats2half2_rn(O[nt][0] * inv0, O[nt][1] * inv0);
        __half2 uB = __floats2half2_rn(O[nt][2] * inv1, O[nt][3] * inv1);
        *(uint32_t*)(y + baseA) = *(uint32_t*)&uA;
        *(uint32_t*)(y + baseB) = *(uint32_t*)&uB;
    }
}

// ---------------------------------------------------------------------------
extern "C" void kernel_launch(void* const* d_in, const int* in_sizes, int n_in,
                              void* d_out, int out_size)
{
    const float* x  = (const float*)d_in[0];
    const float* Wq = (const float*)d_in[1];
    const float* Wk = (const float*)d_in[2];
    const float* Wv = (const float*)d_in[3];
    const float* Wp = (const float*)d_in[4];
    const float* qg = (const float*)d_in[5];
    float* out = (float*)d_out;

    float *q, *kk;
    cudaGetSymbolAddress((void**)&q,  g_q);
    cudaGetSymbolAddress((void**)&kk, g_k);
    __half *xH, *wqH, *wkH, *wvH, *wpH, *qh16, *kh16, *vh16, *yH;
    cudaGetSymbolAddress((void**)&xH,  g_xH);
    cudaGetSymbolAddress((void**)&wqH, g_wqH);
    cudaGetSymbolAddress((void**)&wkH, g_wkH);
    cudaGetSymbolAddress((void**)&wvH, g_wvH);
    cudaGetSymbolAddress((void**)&wpH, g_wpH);
    cudaGetSymbolAddress((void**)&qh16, g_qH);
    cudaGetSymbolAddress((void**)&kh16, g_kH);
    cudaGetSymbolAddress((void**)&vh16, g_vH);
    cudaGetSymbolAddress((void**)&yH,  g_yH);

    cudaFuncSetAttribute(gemm_qkv, cudaFuncAttributeMaxDynamicSharedMemorySize, HSMEM);
    cudaFuncSetAttribute(gemm_out, cudaFuncAttributeMaxDynamicSharedMemorySize, HSMEM);
    cudaFuncSetAttribute(flash_mma, cudaFuncAttributeMaxDynamicSharedMemorySize, FSMEM);

    // (0) RoPE tables, (1) operand prep (pure fp16 conversion)
    rope_table_kernel<<<(T_ * 64 + 255) / 256, 256>>>();
    split_all_kernel<<<SPLIT_TOT / 256, 256>>>(x, Wq, Wk, Wv, Wp);

    // (2) fused Q+K+V projection (1-term fp16), V -> fp16 directly
    gemm_qkv<<<dim3(24, (B_ * T_) / 128), 512, HSMEM>>>(
        xH, wqH, wkH, wvH, q, kk, vh16);

    // (3,4) RMSNorm + RoPE -> fp16 (q folds gain*scale*log2e)
    const float QMUL = 0.08838834764831845f * 1.44269504088896340736f;
    norm_rope_kernel<<<(B_ * T_ * NH_  * 32) / 256, 256>>>(q,  qg,      NH_,  QMUL, qh16);
    norm_rope_kernel<<<(B_ * T_ * NKV_ * 32) / 256, 256>>>(kk, nullptr, NKV_, 1.0f, kh16);

    // (5) flash attention -> y fp16
    flash_mma<<<dim3(T_ / 128, NH_, B_), 256, FSMEM>>>(qh16, kh16, vh16, yH);

    // (6) out projection -> fp32 out
    gemm_out<<<dim3(DIM_ / 128, (B_ * T_) / 128), 512, HSMEM>>>(
        yH, wpH, out, DIM_, DIM_);
}

// round 13
// speedup vs baseline: 1.1747x; 1.0138x over previous
#include <cuda_runtime.h>
#include <cuda_bf16.h>
#include <cuda_fp16.h>
#include <math.h>
#include <stdint.h>

#define B_    2
#define T_    2048
#define DIM_  2048
#define NH_   16
#define NKV_  4
#define HD_   128
#define KD_   512
#define GQ_   (NH_ / NKV_)
#define EPS_  1.1920928955078125e-07f

// ---------------- scratch ----------------------------------------------------
__device__ float g_cos[T_ * (HD_ / 2)];
__device__ float g_sin[T_ * (HD_ / 2)];
__device__ __half g_xH[(size_t)B_ * T_ * DIM_];
__device__ __half g_wqH[(size_t)DIM_ * DIM_];
__device__ __half g_wkH[(size_t)KD_ * DIM_];
__device__ __half g_wvH[(size_t)KD_ * DIM_];
__device__ __half g_wpH[(size_t)DIM_ * DIM_];
__device__ __half g_qH[(size_t)B_ * T_ * DIM_];
__device__ __half g_kH[(size_t)B_ * T_ * KD_];
__device__ __half g_vH[(size_t)B_ * T_ * KD_];
__device__ __half g_yH[(size_t)B_ * T_ * DIM_];

// ---------------- helpers ----------------------------------------------------
__device__ __forceinline__ uint32_t smem_u32(const void* p) {
    uint32_t a;
    asm("{ .reg .u64 t; cvta.to.shared.u64 t, %1; cvt.u32.u64 %0, t; }"
        : "=r"(a) : "l"(p));
    return a;
}
__device__ __forceinline__ void mma_f16(float* d, const uint32_t* a, const uint32_t* b) {
    asm volatile("mma.sync.aligned.m16n8k16.row.col.f32.f16.f16.f32 "
        "{%0,%1,%2,%3}, {%4,%5,%6,%7}, {%8,%9}, {%0,%1,%2,%3};"
        : "+f"(d[0]), "+f"(d[1]), "+f"(d[2]), "+f"(d[3])
        : "r"(a[0]), "r"(a[1]), "r"(a[2]), "r"(a[3]), "r"(b[0]), "r"(b[1]));
}
__device__ __forceinline__ void ldsm_x4(uint32_t* r, uint32_t addr) {
    asm volatile("ldmatrix.sync.aligned.m8n8.x4.shared.b16 {%0,%1,%2,%3}, [%4];"
        : "=r"(r[0]), "=r"(r[1]), "=r"(r[2]), "=r"(r[3]) : "r"(addr));
}
__device__ __forceinline__ void ldsm_x4_t(uint32_t* r, uint32_t addr) {
    asm volatile("ldmatrix.sync.aligned.m8n8.x4.trans.shared.b16 {%0,%1,%2,%3}, [%4];"
        : "=r"(r[0]), "=r"(r[1]), "=r"(r[2]), "=r"(r[3]) : "r"(addr));
}
__device__ __forceinline__ void cp16(uint32_t dst, const void* src) {
    asm volatile("cp.async.cg.shared.global [%0], [%1], 16;" :: "r"(dst), "l"(src));
}
#define CP_COMMIT() asm volatile("cp.async.commit_group;" ::: "memory")
#define CP_WAIT0()  asm volatile("cp.async.wait_group 0;" ::: "memory")
#define CP_WAIT2()  asm volatile("cp.async.wait_group 2;" ::: "memory")

__device__ __forceinline__ uint2 tohalf4(float4 f) {
    __half2 h0 = __floats2half2_rn(f.x, f.y);
    __half2 h1 = __floats2half2_rn(f.z, f.w);
    return make_uint2(*(uint32_t*)&h0, *(uint32_t*)&h1);
}
#define NEG_INF __int_as_float(0xff800000)

// ---------------- RoPE tables ------------------------------------------------
__global__ void rope_table_kernel() {
    int idx = blockIdx.x * blockDim.x + threadIdx.x;
    if (idx >= T_ * (HD_ / 2)) return;
    int t = idx >> 6;
    int i = idx & 63;
    double base = 10000.0;
    if (T_ > 1024)
        base = 10000.0 * pow((double)T_ / 1024.0, (double)HD_ / (double)(HD_ - 2));
    double f = pow(base, -((double)(2 * i)) / (double)HD_);
    double a = (double)t * f;
    g_cos[idx] = (float)cos(a);
    g_sin[idx] = (float)sin(a);
}

// ---------------- operand prep: fp32 -> fp16 ----------------------------------
#define S_X   (B_ * T_ * DIM_ / 4)
#define S_WQ  (DIM_ * DIM_ / 4)
#define S_WK  (KD_ * DIM_ / 4)
#define SPLIT_TOT (S_X + S_WQ + S_WK + S_WK + S_WQ)

__global__ void split_all_kernel(const float* __restrict__ x,
                                 const float* __restrict__ Wq,
                                 const float* __restrict__ Wk,
                                 const float* __restrict__ Wv,
                                 const float* __restrict__ Wp)
{
    int i = blockIdx.x * blockDim.x + threadIdx.x;
    if (i < S_X)  { ((uint2*)g_xH)[i]  = tohalf4(((const float4*)x)[i]);  return; }
    i -= S_X;
    if (i < S_WQ) { ((uint2*)g_wqH)[i] = tohalf4(((const float4*)Wq)[i]); return; }
    i -= S_WQ;
    if (i < S_WK) { ((uint2*)g_wkH)[i] = tohalf4(((const float4*)Wk)[i]); return; }
    i -= S_WK;
    if (i < S_WK) { ((uint2*)g_wvH)[i] = tohalf4(((const float4*)Wv)[i]); return; }
    i -= S_WK;
    ((uint2*)g_wpH)[i] = tohalf4(((const float4*)Wp)[i]);
}

// ---------------- 1-term fp16 GEMM body (512 thr, 4-stage) ---------------------
// Epilogue kinds: 0 = fp32 C, 1 = fp16 Ch, 2 = RMSNorm+RoPE(+gain) -> fp16 Ch
// For kind 2, the CTA's 128-col output tile is exactly one head; ld = row stride
// of the fp16 output, coff = head * 128.
#define HST     144
#define HPART   (128 * HST)
#define HSTAGE  (2 * HPART)
#define HSMEM   (4 * HSTAGE)

template<int KIND>
__device__ __forceinline__ void gemm1_body(
    const __half* __restrict__ A, const __half* __restrict__ W,
    float* __restrict__ C, __half* __restrict__ Ch,
    int N, int K, int bm, int bn, float post_mul)
{
    extern __shared__ char sm[];
    const uint32_t sb = smem_u32(sm);
    const int tid = threadIdx.x, wid = tid >> 5, lane = tid & 31;
    const int wm = wid & 3, wn = wid >> 2;

    float acc[2][4][4];
    #pragma unroll
    for (int i = 0; i < 2; ++i)
        #pragma unroll
        for (int j = 0; j < 4; ++j)
            #pragma unroll
            for (int q = 0; q < 4; ++q) acc[i][j][q] = 0.f;

    const int niter = K / 64;

    auto load_stage = [&](int it, int buf) {
        const int k0 = it * 64;
        const uint32_t s = sb + buf * HSTAGE;
        #pragma unroll
        for (int p = 0; p < 4; ++p) {
            int idx  = tid + p * 512;
            int part = idx >> 10;
            int r    = (idx >> 3) & 127;
            int c    = idx & 7;
            const __half* src = part ? W : A;
            int rowg = (part ? bn : bm) + r;
            cp16(s + part * HPART + r * HST + c * 16,
                 src + (size_t)rowg * K + k0 + c * 8);
        }
    };

    load_stage(0, 0); CP_COMMIT();
    load_stage(1, 1); CP_COMMIT();
    load_stage(2, 2); CP_COMMIT();

    for (int it = 0; it < niter; ++it) {
        const int buf = it & 3;
        CP_WAIT2();
        __syncthreads();
        if (it + 3 < niter) { load_stage(it + 3, (it + 3) & 3); CP_COMMIT(); }

        const uint32_t sbuf = sb + buf * HSTAGE;
        #pragma unroll
        for (int ks = 0; ks < 4; ++ks) {
            uint32_t a[2][4], b[2][4];
            #pragma unroll
            for (int mt = 0; mt < 2; ++mt) {
                uint32_t ra = sbuf + (wm * 32 + mt * 16 + (lane & 15)) * HST
                            + ks * 32 + ((lane >> 4) << 4);
                ldsm_x4(a[mt], ra);
            }
            #pragma unroll
            for (int pr = 0; pr < 2; ++pr) {
                uint32_t rb = sbuf + HPART
                            + (wn * 32 + pr * 16 + (lane & 7) + ((lane >> 4) << 3)) * HST
                            + ks * 32 + (((lane >> 3) & 1) << 4);
                ldsm_x4(b[pr], rb);
            }
            #pragma unroll
            for (int mt = 0; mt < 2; ++mt)
                #pragma unroll
                for (int nt = 0; nt < 4; ++nt)
                    mma_f16(acc[mt][nt], a[mt], b[nt >> 1] + (nt & 1) * 2);
        }
        __syncthreads();
    }

    if (KIND == 0 || KIND == 1) {
        #pragma unroll
        for (int mt = 0; mt < 2; ++mt)
            #pragma unroll
            for (int nt = 0; nt < 4; ++nt) {
                int row = bm + wm * 32 + mt * 16 + (lane >> 2);
                int col = bn + wn * 32 + nt * 8 + 2 * (lane & 3);
                if (KIND == 1) {
                    __half2 u0 = __floats2half2_rn(acc[mt][nt][0], acc[mt][nt][1]);
                    __half2 u1 = __floats2half2_rn(acc[mt][nt][2], acc[mt][nt][3]);
                    *(uint32_t*)(Ch + (size_t)row * N + col)       = *(uint32_t*)&u0;
                    *(uint32_t*)(Ch + (size_t)(row + 8) * N + col) = *(uint32_t*)&u1;
                } else {
                    *(float2*)(C + (size_t)row * N + col) =
                        make_float2(acc[mt][nt][0], acc[mt][nt][1]);
                    *(float2*)(C + (size_t)(row + 8) * N + col) =
                        make_float2(acc[mt][nt][2], acc[mt][nt][3]);
                }
            }
        return;
    }

    // ---- KIND == 2: fused RMSNorm + RoPE epilogue (tile = one head) ----
    // ld = N (fp16 output row stride), head col offset = bn.
    float* ssq_sm = (float*)sm;                    // [128][4]
    float* tile   = (float*)(sm + 2048);           // [128][132]

    // per-thread partial sum of squares: 4 rows x 8 cols
    float ssq[2][2];
    #pragma unroll
    for (int mt = 0; mt < 2; ++mt)
        #pragma unroll
        for (int hf = 0; hf < 2; ++hf) {
            float s = 0.f;
            #pragma unroll
            for (int nt = 0; nt < 4; ++nt) {
                float v0 = acc[mt][nt][hf * 2 + 0];
                float v1 = acc[mt][nt][hf * 2 + 1];
                s += v0 * v0 + v1 * v1;
            }
            s += __shfl_xor_sync(0xffffffffu, s, 1);
            s += __shfl_xor_sync(0xffffffffu, s, 2);
            ssq[mt][hf] = s;
        }
    if ((lane & 3) == 0) {
        #pragma unroll
        for (int mt = 0; mt < 2; ++mt)
            #pragma unroll
            for (int hf = 0; hf < 2; ++hf) {
                int row = wm * 32 + mt * 16 + hf * 8 + (lane >> 2);
                ssq_sm[row * 4 + wn] = ssq[mt][hf];
            }
    }
    __syncthreads();

    // normalize and stage to smem tile
    #pragma unroll
    for (int mt = 0; mt < 2; ++mt)
        #pragma unroll
        for (int hf = 0; hf < 2; ++hf) {
            int row = wm * 32 + mt * 16 + hf * 8 + (lane >> 2);
            float tot = ssq_sm[row * 4 + 0] + ssq_sm[row * 4 + 1]
                      + ssq_sm[row * 4 + 2] + ssq_sm[row * 4 + 3];
            float rr = rsqrtf(tot * (1.f / HD_) + EPS_) * post_mul;
            #pragma unroll
            for (int nt = 0; nt < 4; ++nt) {
                int col = wn * 32 + nt * 8 + 2 * (lane & 3);
                tile[row * 132 + col]     = acc[mt][nt][hf * 2 + 0] * rr;
                tile[row * 132 + col + 1] = acc[mt][nt][hf * 2 + 1] * rr;
            }
        }
    __syncthreads();

    // RoPE from staged tile -> fp16 output
    #pragma unroll
    for (int mt = 0; mt < 2; ++mt)
        #pragma unroll
        for (int hf = 0; hf < 2; ++hf) {
            int row = wm * 32 + mt * 16 + hf * 8 + (lane >> 2);
            int t   = (bm + row) & (T_ - 1);
            #pragma unroll
            for (int nt = 0; nt < 4; ++nt) {
                int col = wn * 32 + nt * 8 + 2 * (lane & 3);
                float o[2];
                #pragma unroll
                for (int e = 0; e < 2; ++e) {
                    int c0 = col + e;
                    float own = tile[row * 132 + c0];
                    float par = tile[row * 132 + (c0 ^ 64)];
                    int i = c0 & 63;
                    float cs = g_cos[t * 64 + i];
                    float sn = g_sin[t * 64 + i];
                    o[e] = (c0 < 64) ? (own * cs + par * sn)
                                     : (own * cs - par * sn);
                }
                __half2 u = __floats2half2_rn(o[0], o[1]);
                *(uint32_t*)(Ch + (size_t)(bm + row) * N + bn + col) = *(uint32_t*)&u;
            }
        }
}

// fused QKV projection + norm/rope: tiles 0..15 -> Q, 16..19 -> K, 20..23 -> V
__global__ void __launch_bounds__(512, 1) gemm_qkv(
    const __half* __restrict__ xH,
    const __half* __restrict__ wq, const __half* __restrict__ wk,
    const __half* __restrict__ wv, const float* __restrict__ qg,
    __half* __restrict__ qO, __half* __restrict__ kO, __half* __restrict__ vO)
{
    const int bx = blockIdx.x;
    const float QMUL = 0.08838834764831845f * 1.44269504088896340736f;
    if (bx < 16) {
        float pm = qg[bx] * QMUL;
        gemm1_body<2>(xH, wq, nullptr, qO, DIM_, DIM_,
                      blockIdx.y * 128, bx * 128, pm);
    } else if (bx < 20) {
        gemm1_body<2>(xH, wk, nullptr, kO, KD_, DIM_,
                      blockIdx.y * 128, (bx - 16) * 128, 1.0f);
    } else {
        gemm1_body<1>(xH, wv, nullptr, vO, KD_, DIM_,
                      blockIdx.y * 128, (bx - 20) * 128, 1.0f);
    }
}

// out projection
__global__ void __launch_bounds__(512, 1) gemm_out(
    const __half* __restrict__ A, const __half* __restrict__ W,
    float* __restrict__ C, int N, int K)
{
    gemm1_body<0>(A, W, C, nullptr, N, K, blockIdx.y * 128, blockIdx.x * 128, 1.0f);
}

// ---------------- flash attention: 1-term fp16, Q in registers ----------------
#define FST    272
#define QT     (128 * FST)
#define KVP    (64 * FST)
#define STG    (2 * KVP)
#define FSMEM  (QT + 2 * STG)

__global__ void __launch_bounds__(256, 1) flash_mma(
    const __half* __restrict__ qH, const __half* __restrict__ kH,
    const __half* __restrict__ vH, __half* __restrict__ y)
{
    extern __shared__ char sm[];
    const uint32_t sb = smem_u32(sm);
    const int tid = threadIdx.x, wid = tid >> 5, lane = tid & 31;
    const int itq = (gridDim.x - 1) - blockIdx.x;
    const int h = blockIdx.y, b = blockIdx.z;
    const int kvh = h / GQ_;
    const int t0q = itq * 128;
    const int jmax = 2 * itq + 1;

    #pragma unroll
    for (int p = 0; p < 8; ++p) {
        int idx = tid + p * 256;
        int r = (idx >> 4) & 127, c = idx & 15;
        cp16(sb + r * FST + c * 16,
             qH + ((size_t)(b * T_ + t0q + r) * NH_ + h) * HD_ + c * 8);
    }
    #pragma unroll
    for (int p = 0; p < 8; ++p) {
        int idx = tid + p * 256;
        int part = idx >> 10;
        int r = (idx >> 4) & 63, c = idx & 15;
        const __half* src = part ? vH : kH;
        cp16(sb + QT + part * KVP + r * FST + c * 16,
             src + ((size_t)(b * T_ + r) * NKV_ + kvh) * HD_ + c * 8);
    }
    CP_COMMIT();
    CP_WAIT0();
    __syncthreads();

    uint32_t QF[8][4];
    #pragma unroll
    for (int ks = 0; ks < 8; ++ks) {
        uint32_t ra = sb + (wid * 16 + (lane & 15)) * FST
                    + ks * 32 + ((lane >> 4) << 4);
        ldsm_x4(QF[ks], ra);
    }

    float m0 = NEG_INF, m1 = NEG_INF, l0 = 0.f, l1 = 0.f;
    float O[16][4];
    #pragma unroll
    for (int nt = 0; nt < 16; ++nt)
        #pragma unroll
        for (int j = 0; j < 4; ++j) O[nt][j] = 0.f;

    const int row_a = t0q + wid * 16 + (lane >> 2);

    for (int jt = 0; jt <= jmax; ++jt) {
        const int buf = jt & 1;
        if (jt > 0) { CP_WAIT0(); __syncthreads(); }
        if (jt + 1 <= jmax) {
            const int t0n = (jt + 1) * 64;
            #pragma unroll
            for (int p = 0; p < 8; ++p) {
                int idx = tid + p * 256;
                int part = idx >> 10;
                int r = (idx >> 4) & 63, c = idx & 15;
                const __half* src = part ? vH : kH;
                cp16(sb + QT + (buf ^ 1) * STG + part * KVP + r * FST + c * 16,
                     src + ((size_t)(b * T_ + t0n + r) * NKV_ + kvh) * HD_ + c * 8);
            }
            CP_COMMIT();
        }

        const uint32_t base_k = sb + QT + buf * STG;
        const int t0k = jt * 64;

        float S[8][4];
        #pragma unroll
        for (int nt = 0; nt < 8; ++nt)
            #pragma unroll
            for (int j = 0; j < 4; ++j) S[nt][j] = 0.f;

        #pragma unroll
        for (int ks = 0; ks < 8; ++ks) {
            #pragma unroll
            for (int ntp = 0; ntp < 4; ++ntp) {
                uint32_t bh[4];
                uint32_t rb = base_k
                            + (ntp * 16 + (lane & 7) + ((lane >> 4) << 3)) * FST
                            + ks * 32 + (((lane >> 3) & 1) << 4);
                ldsm_x4(bh, rb);
                mma_f16(S[2 * ntp],     QF[ks], bh);
                mma_f16(S[2 * ntp + 1], QF[ks], bh + 2);
            }
        }

        const bool diag = (jt >= 2 * itq);
        float ml0 = NEG_INF, ml1 = NEG_INF;
        #pragma unroll
        for (int nt = 0; nt < 8; ++nt) {
            int c = t0k + nt * 8 + 2 * (lane & 3);
            if (diag) {
                if (c     > row_a)     S[nt][0] = NEG_INF;
                if (c + 1 > row_a)     S[nt][1] = NEG_INF;
                if (c     > row_a + 8) S[nt][2] = NEG_INF;
                if (c + 1 > row_a + 8) S[nt][3] = NEG_INF;
            }
            ml0 = fmaxf(ml0, fmaxf(S[nt][0], S[nt][1]));
            ml1 = fmaxf(ml1, fmaxf(S[nt][2], S[nt][3]));
        }
        ml0 = fmaxf(ml0, __shfl_xor_sync(0xffffffffu, ml0, 1));
        ml0 = fmaxf(ml0, __shfl_xor_sync(0xffffffffu, ml0, 2));
        ml1 = fmaxf(ml1, __shfl_xor_sync(0xffffffffu, ml1, 1));
        ml1 = fmaxf(ml1, __shfl_xor_sync(0xffffffffu, ml1, 2));

        float mn0 = fmaxf(m0, ml0), mn1 = fmaxf(m1, ml1);
        float es0 = exp2f(m0 - mn0);
        float es1 = exp2f(m1 - mn1);
        m0 = mn0; m1 = mn1;

        float sum0 = 0.f, sum1 = 0.f;
        uint32_t PH[16];
        #pragma unroll
        for (int nt = 0; nt < 8; ++nt) {
            float p0 = exp2f(S[nt][0] - mn0);
            float p1 = exp2f(S[nt][1] - mn0);
            float p2 = exp2f(S[nt][2] - mn1);
            float p3 = exp2f(S[nt][3] - mn1);
            sum0 += p0 + p1;  sum1 += p2 + p3;
            __half2 hA = __floats2half2_rn(p0, p1);
            __half2 hB = __floats2half2_rn(p2, p3);
            PH[2 * nt]     = *(uint32_t*)&hA;
            PH[2 * nt + 1] = *(uint32_t*)&hB;
        }
        sum0 += __shfl_xor_sync(0xffffffffu, sum0, 1);
        sum0 += __shfl_xor_sync(0xffffffffu, sum0, 2);
        sum1 += __shfl_xor_sync(0xffffffffu, sum1, 1);
        sum1 += __shfl_xor_sync(0xffffffffu, sum1, 2);
        l0 = l0 * es0 + sum0;
        l1 = l1 * es1 + sum1;
        #pragma unroll
        for (int nt = 0; nt < 16; ++nt) {
            O[nt][0] *= es0; O[nt][1] *= es0;
            O[nt][2] *= es1; O[nt][3] *= es1;
        }

        const uint32_t base_v = base_k + KVP;
        #pragma unroll
        for (int kt = 0; kt < 4; ++kt) {
            uint32_t pa[4] = { PH[4*kt], PH[4*kt+1], PH[4*kt+2], PH[4*kt+3] };
            #pragma unroll
            for (int ntp = 0; ntp < 8; ++ntp) {
                uint32_t bh[4];
                uint32_t rv = base_v
                            + (kt * 16 + (lane & 7) + (lane & 8)) * FST
                            + ntp * 32 + ((lane >> 4) << 4);
                ldsm_x4_t(bh, rv);
                mma_f16(O[2 * ntp],     pa, bh);
                mma_f16(O[2 * ntp + 1], pa, bh + 2);
            }
        }
    }

    float inv0 = 1.f / l0, inv1 = 1.f / l1;
    #pragma unroll
    for (int nt = 0; nt < 16; ++nt) {
        int c = nt * 8 + 2 * (lane & 3);
        size_t baseA = ((size_t)(b * T_ + row_a) * NH_ + h) * HD_ + c;
        size_t baseB = ((size_t)(b * T_ + row_a + 8) * NH_ + h) * HD_ + c;
        __half2 uA = __floats2half2_rn(O[nt][0] * inv0, O[nt][1] * inv0);
        __half2 uB = __floats2half2_rn(O[nt][2] * inv1, O[nt][3] * inv1);
        *(uint32_t*)(y + baseA) = *(uint32_t*)&uA;
        *(uint32_t*)(y + baseB) = *(uint32_t*)&uB;
    }
}

// ---------------------------------------------------------------------------
extern "C" void kernel_launch(void* const* d_in, const int* in_sizes, int n_in,
                              void* d_out, int out_size)
{
    const float* x  = (const float*)d_in[0];
    const float* Wq = (const float*)d_in[1];
    const float* Wk = (const float*)d_in[2];
    const float* Wv = (const float*)d_in[3];
    const float* Wp = (const float*)d_in[4];
    const float* qg = (const float*)d_in[5];
    float* out = (float*)d_out;

    __half *xH, *wqH, *wkH, *wvH, *wpH, *qh16, *kh16, *vh16, *yH;
    cudaGetSymbolAddress((void**)&xH,  g_xH);
    cudaGetSymbolAddress((void**)&wqH, g_wqH);
    cudaGetSymbolAddress((void**)&wkH, g_wkH);
    cudaGetSymbolAddress((void**)&wvH, g_wvH);
    cudaGetSymbolAddress((void**)&wpH, g_wpH);
    cudaGetSymbolAddress((void**)&qh16, g_qH);
    cudaGetSymbolAddress((void**)&kh16, g_kH);
    cudaGetSymbolAddress((void**)&vh16, g_vH);
    cudaGetSymbolAddress((void**)&yH,  g_yH);

    cudaFuncSetAttribute(gemm_qkv, cudaFuncAttributeMaxDynamicSharedMemorySize, HSMEM);
    cudaFuncSetAttribute(gemm_out, cudaFuncAttributeMaxDynamicSharedMemorySize, HSMEM);
    cudaFuncSetAttribute(flash_mma, cudaFuncAttributeMaxDynamicSharedMemorySize, FSMEM);

    // (0) RoPE tables, (1) operand prep (pure fp16 conversion)
    rope_table_kernel<<<(T_ * 64 + 255) / 256, 256>>>();
    split_all_kernel<<<SPLIT_TOT / 256, 256>>>(x, Wq, Wk, Wv, Wp);

    // (2) fused Q+K+V projection with RMSNorm+RoPE epilogue -> fp16
    gemm_qkv<<<dim3(24, (B_ * T_) / 128), 512, HSMEM>>>(
        xH, wqH, wkH, wvH, qg, qh16, kh16, vh16);

    // (3) flash attention -> y fp16
    flash_mma<<<dim3(T_ / 128, NH_, B_), 256, FSMEM>>>(qh16, kh16, vh16, yH);

    // (4) out projection -> fp32 out
    gemm_out<<<dim3(DIM_ / 128, (B_ * T_) / 128), 512, HSMEM>>>(
        yH, wpH, out, DIM_, DIM_);
}

// round 14
// speedup vs baseline: 1.1917x; 1.0144x over previous
#include <cuda_runtime.h>
#include <cuda_bf16.h>
#include <cuda_fp16.h>
#include <math.h>
#include <stdint.h>

#define B_    2
#define T_    2048
#define DIM_  2048
#define NH_   16
#define NKV_  4
#define HD_   128
#define KD_   512
#define GQ_   (NH_ / NKV_)
#define EPS_  1.1920928955078125e-07f

// ---------------- scratch ----------------------------------------------------
__device__ float g_cos[T_ * (HD_ / 2)];
__device__ float g_sin[T_ * (HD_ / 2)];
__device__ __half g_xH[(size_t)B_ * T_ * DIM_];
__device__ __half g_wqH[(size_t)DIM_ * DIM_];
__device__ __half g_wkH[(size_t)KD_ * DIM_];
__device__ __half g_wvH[(size_t)KD_ * DIM_];
__device__ __half g_wpH[(size_t)DIM_ * DIM_];
__device__ __half g_qH[(size_t)B_ * T_ * DIM_];
__device__ __half g_kH[(size_t)B_ * T_ * KD_];
__device__ __half g_vH[(size_t)B_ * T_ * KD_];
__device__ __half g_yH[(size_t)B_ * T_ * DIM_];

// ---------------- helpers ----------------------------------------------------
__device__ __forceinline__ uint32_t smem_u32(const void* p) {
    uint32_t a;
    asm("{ .reg .u64 t; cvta.to.shared.u64 t, %1; cvt.u32.u64 %0, t; }"
        : "=r"(a) : "l"(p));
    return a;
}
__device__ __forceinline__ void mma_f16(float* d, const uint32_t* a, const uint32_t* b) {
    asm volatile("mma.sync.aligned.m16n8k16.row.col.f32.f16.f16.f32 "
        "{%0,%1,%2,%3}, {%4,%5,%6,%7}, {%8,%9}, {%0,%1,%2,%3};"
        : "+f"(d[0]), "+f"(d[1]), "+f"(d[2]), "+f"(d[3])
        : "r"(a[0]), "r"(a[1]), "r"(a[2]), "r"(a[3]), "r"(b[0]), "r"(b[1]));
}
__device__ __forceinline__ void ldsm_x4(uint32_t* r, uint32_t addr) {
    asm volatile("ldmatrix.sync.aligned.m8n8.x4.shared.b16 {%0,%1,%2,%3}, [%4];"
        : "=r"(r[0]), "=r"(r[1]), "=r"(r[2]), "=r"(r[3]) : "r"(addr));
}
__device__ __forceinline__ void ldsm_x4_t(uint32_t* r, uint32_t addr) {
    asm volatile("ldmatrix.sync.aligned.m8n8.x4.trans.shared.b16 {%0,%1,%2,%3}, [%4];"
        : "=r"(r[0]), "=r"(r[1]), "=r"(r[2]), "=r"(r[3]) : "r"(addr));
}
__device__ __forceinline__ void cp16(uint32_t dst, const void* src) {
    asm volatile("cp.async.cg.shared.global [%0], [%1], 16;" :: "r"(dst), "l"(src));
}
#define CP_COMMIT() asm volatile("cp.async.commit_group;" ::: "memory")
#define CP_WAIT0()  asm volatile("cp.async.wait_group 0;" ::: "memory")
#define CP_WAIT2()  asm volatile("cp.async.wait_group 2;" ::: "memory")

__device__ __forceinline__ uint2 tohalf4(float4 f) {
    __half2 h0 = __floats2half2_rn(f.x, f.y);
    __half2 h1 = __floats2half2_rn(f.z, f.w);
    return make_uint2(*(uint32_t*)&h0, *(uint32_t*)&h1);
}
#define NEG_INF __int_as_float(0xff800000)

// ---------------- RoPE tables ------------------------------------------------
__global__ void rope_table_kernel() {
    int idx = blockIdx.x * blockDim.x + threadIdx.x;
    if (idx >= T_ * (HD_ / 2)) return;
    int t = idx >> 6;
    int i = idx & 63;
    double base = 10000.0;
    if (T_ > 1024)
        base = 10000.0 * pow((double)T_ / 1024.0, (double)HD_ / (double)(HD_ - 2));
    double f = pow(base, -((double)(2 * i)) / (double)HD_);
    double a = (double)t * f;
    g_cos[idx] = (float)cos(a);
    g_sin[idx] = (float)sin(a);
}

// ---------------- operand prep: fp32 -> fp16, 4-way ILP ------------------------
#define S_X   (B_ * T_ * DIM_ / 4)
#define S_WQ  (DIM_ * DIM_ / 4)
#define S_WK  (KD_ * DIM_ / 4)
#define SPLIT_TOT (S_X + S_WQ + S_WK + S_WK + S_WQ)

__device__ __forceinline__ void split_one(int i,
    const float* x, const float* Wq, const float* Wk,
    const float* Wv, const float* Wp)
{
    if (i < S_X)  { ((uint2*)g_xH)[i]  = tohalf4(((const float4*)x)[i]);  return; }
    i -= S_X;
    if (i < S_WQ) { ((uint2*)g_wqH)[i] = tohalf4(((const float4*)Wq)[i]); return; }
    i -= S_WQ;
    if (i < S_WK) { ((uint2*)g_wkH)[i] = tohalf4(((const float4*)Wk)[i]); return; }
    i -= S_WK;
    if (i < S_WK) { ((uint2*)g_wvH)[i] = tohalf4(((const float4*)Wv)[i]); return; }
    i -= S_WK;
    ((uint2*)g_wpH)[i] = tohalf4(((const float4*)Wp)[i]);
}

__global__ void split_all_kernel(const float* __restrict__ x,
                                 const float* __restrict__ Wq,
                                 const float* __restrict__ Wk,
                                 const float* __restrict__ Wv,
                                 const float* __restrict__ Wp)
{
    int base = blockIdx.x * 1024 + threadIdx.x;
    #pragma unroll
    for (int k = 0; k < 4; ++k) {
        int i = base + k * 256;
        if (i < SPLIT_TOT) split_one(i, x, Wq, Wk, Wv, Wp);
    }
}

// ---------------- 1-term fp16 GEMM body (512 thr, 4-stage) ---------------------
#define HST     144
#define HPART   (128 * HST)
#define HSTAGE  (2 * HPART)
#define HSMEM   (4 * HSTAGE)

template<int KIND>
__device__ __forceinline__ void gemm1_body(
    const __half* __restrict__ A, const __half* __restrict__ W,
    float* __restrict__ C, __half* __restrict__ Ch,
    int N, int K, int bm, int bn, float post_mul)
{
    extern __shared__ char sm[];
    const uint32_t sb = smem_u32(sm);
    const int tid = threadIdx.x, wid = tid >> 5, lane = tid & 31;
    const int wm = wid & 3, wn = wid >> 2;

    float acc[2][4][4];
    #pragma unroll
    for (int i = 0; i < 2; ++i)
        #pragma unroll
        for (int j = 0; j < 4; ++j)
            #pragma unroll
            for (int q = 0; q < 4; ++q) acc[i][j][q] = 0.f;

    const int niter = K / 64;

    auto load_stage = [&](int it, int buf) {
        const int k0 = it * 64;
        const uint32_t s = sb + buf * HSTAGE;
        #pragma unroll
        for (int p = 0; p < 4; ++p) {
            int idx  = tid + p * 512;
            int part = idx >> 10;
            int r    = (idx >> 3) & 127;
            int c    = idx & 7;
            const __half* src = part ? W : A;
            int rowg = (part ? bn : bm) + r;
            cp16(s + part * HPART + r * HST + c * 16,
                 src + (size_t)rowg * K + k0 + c * 8);
        }
    };

    load_stage(0, 0); CP_COMMIT();
    load_stage(1, 1); CP_COMMIT();
    load_stage(2, 2); CP_COMMIT();

    for (int it = 0; it < niter; ++it) {
        const int buf = it & 3;
        CP_WAIT2();
        __syncthreads();
        if (it + 3 < niter) { load_stage(it + 3, (it + 3) & 3); CP_COMMIT(); }

        const uint32_t sbuf = sb + buf * HSTAGE;
        #pragma unroll
        for (int ks = 0; ks < 4; ++ks) {
            uint32_t a[2][4], b[2][4];
            #pragma unroll
            for (int mt = 0; mt < 2; ++mt) {
                uint32_t ra = sbuf + (wm * 32 + mt * 16 + (lane & 15)) * HST
                            + ks * 32 + ((lane >> 4) << 4);
                ldsm_x4(a[mt], ra);
            }
            #pragma unroll
            for (int pr = 0; pr < 2; ++pr) {
                uint32_t rb = sbuf + HPART
                            + (wn * 32 + pr * 16 + (lane & 7) + ((lane >> 4) << 3)) * HST
                            + ks * 32 + (((lane >> 3) & 1) << 4);
                ldsm_x4(b[pr], rb);
            }
            #pragma unroll
            for (int mt = 0; mt < 2; ++mt)
                #pragma unroll
                for (int nt = 0; nt < 4; ++nt)
                    mma_f16(acc[mt][nt], a[mt], b[nt >> 1] + (nt & 1) * 2);
        }
        __syncthreads();
    }

    if (KIND == 0 || KIND == 1) {
        #pragma unroll
        for (int mt = 0; mt < 2; ++mt)
            #pragma unroll
            for (int nt = 0; nt < 4; ++nt) {
                int row = bm + wm * 32 + mt * 16 + (lane >> 2);
                int col = bn + wn * 32 + nt * 8 + 2 * (lane & 3);
                if (KIND == 1) {
                    __half2 u0 = __floats2half2_rn(acc[mt][nt][0], acc[mt][nt][1]);
                    __half2 u1 = __floats2half2_rn(acc[mt][nt][2], acc[mt][nt][3]);
                    *(uint32_t*)(Ch + (size_t)row * N + col)       = *(uint32_t*)&u0;
                    *(uint32_t*)(Ch + (size_t)(row + 8) * N + col) = *(uint32_t*)&u1;
                } else {
                    *(float2*)(C + (size_t)row * N + col) =
                        make_float2(acc[mt][nt][0], acc[mt][nt][1]);
                    *(float2*)(C + (size_t)(row + 8) * N + col) =
                        make_float2(acc[mt][nt][2], acc[mt][nt][3]);
                }
            }
        return;
    }

    // ---- KIND == 2: fused RMSNorm + RoPE epilogue (tile = one head) ----
    float* ssq_sm = (float*)sm;
    float* tile   = (float*)(sm + 2048);           // [128][132]

    float ssq[2][2];
    #pragma unroll
    for (int mt = 0; mt < 2; ++mt)
        #pragma unroll
        for (int hf = 0; hf < 2; ++hf) {
            float s = 0.f;
            #pragma unroll
            for (int nt = 0; nt < 4; ++nt) {
                float v0 = acc[mt][nt][hf * 2 + 0];
                float v1 = acc[mt][nt][hf * 2 + 1];
                s += v0 * v0 + v1 * v1;
            }
            s += __shfl_xor_sync(0xffffffffu, s, 1);
            s += __shfl_xor_sync(0xffffffffu, s, 2);
            ssq[mt][hf] = s;
        }
    if ((lane & 3) == 0) {
        #pragma unroll
        for (int mt = 0; mt < 2; ++mt)
            #pragma unroll
            for (int hf = 0; hf < 2; ++hf) {
                int row = wm * 32 + mt * 16 + hf * 8 + (lane >> 2);
                ssq_sm[row * 4 + wn] = ssq[mt][hf];
            }
    }
    __syncthreads();

    #pragma unroll
    for (int mt = 0; mt < 2; ++mt)
        #pragma unroll
        for (int hf = 0; hf < 2; ++hf) {
            int row = wm * 32 + mt * 16 + hf * 8 + (lane >> 2);
            float tot = ssq_sm[row * 4 + 0] + ssq_sm[row * 4 + 1]
                      + ssq_sm[row * 4 + 2] + ssq_sm[row * 4 + 3];
            float rr = rsqrtf(tot * (1.f / HD_) + EPS_) * post_mul;
            #pragma unroll
            for (int nt = 0; nt < 4; ++nt) {
                int col = wn * 32 + nt * 8 + 2 * (lane & 3);
                tile[row * 132 + col]     = acc[mt][nt][hf * 2 + 0] * rr;
                tile[row * 132 + col + 1] = acc[mt][nt][hf * 2 + 1] * rr;
            }
        }
    __syncthreads();

    #pragma unroll
    for (int mt = 0; mt < 2; ++mt)
        #pragma unroll
        for (int hf = 0; hf < 2; ++hf) {
            int row = wm * 32 + mt * 16 + hf * 8 + (lane >> 2);
            int t   = (bm + row) & (T_ - 1);
            #pragma unroll
            for (int nt = 0; nt < 4; ++nt) {
                int col = wn * 32 + nt * 8 + 2 * (lane & 3);
                float o[2];
                #pragma unroll
                for (int e = 0; e < 2; ++e) {
                    int c0 = col + e;
                    float own = tile[row * 132 + c0];
                    float par = tile[row * 132 + (c0 ^ 64)];
                    int i = c0 & 63;
                    float cs = g_cos[t * 64 + i];
                    float sn = g_sin[t * 64 + i];
                    o[e] = (c0 < 64) ? (own * cs + par * sn)
                                     : (own * cs - par * sn);
                }
                __half2 u = __floats2half2_rn(o[0], o[1]);
                *(uint32_t*)(Ch + (size_t)(bm + row) * N + bn + col) = *(uint32_t*)&u;
            }
        }
}

__global__ void __launch_bounds__(512, 1) gemm_qkv(
    const __half* __restrict__ xH,
    const __half* __restrict__ wq, const __half* __restrict__ wk,
    const __half* __restrict__ wv, const float* __restrict__ qg,
    __half* __restrict__ qO, __half* __restrict__ kO, __half* __restrict__ vO)
{
    const int bx = blockIdx.x;
    const float QMUL = 0.08838834764831845f * 1.44269504088896340736f;
    if (bx < 16) {
        float pm = qg[bx] * QMUL;
        gemm1_body<2>(xH, wq, nullptr, qO, DIM_, DIM_,
                      blockIdx.y * 128, bx * 128, pm);
    } else if (bx < 20) {
        gemm1_body<2>(xH, wk, nullptr, kO, KD_, DIM_,
                      blockIdx.y * 128, (bx - 16) * 128, 1.0f);
    } else {
        gemm1_body<1>(xH, wv, nullptr, vO, KD_, DIM_,
                      blockIdx.y * 128, (bx - 20) * 128, 1.0f);
    }
}

__global__ void __launch_bounds__(512, 1) gemm_out(
    const __half* __restrict__ A, const __half* __restrict__ W,
    float* __restrict__ C, int N, int K)
{
    gemm1_body<0>(A, W, C, nullptr, N, K, blockIdx.y * 128, blockIdx.x * 128, 1.0f);
}

// ---------------- flash attention: fp16, 128-key KV tiles ----------------------
#define FST     272
#define QT      (128 * FST)          // 34816
#define KVP2    (128 * FST)          // 34816 per tensor
#define STG2    (2 * KVP2)           // 69632
#define FSMEM2  (QT + 2 * STG2)      // 174080

__global__ void __launch_bounds__(256, 1) flash_mma(
    const __half* __restrict__ qH, const __half* __restrict__ kH,
    const __half* __restrict__ vH, __half* __restrict__ y)
{
    extern __shared__ char sm[];
    const uint32_t sb = smem_u32(sm);
    const int tid = threadIdx.x, wid = tid >> 5, lane = tid & 31;
    const int itq = (gridDim.x - 1) - blockIdx.x;
    const int h = blockIdx.y, b = blockIdx.z;
    const int kvh = h / GQ_;
    const int t0q = itq * 128;

    // Q tile
    #pragma unroll
    for (int p = 0; p < 8; ++p) {
        int idx = tid + p * 256;
        int r = (idx >> 4) & 127, c = idx & 15;
        cp16(sb + r * FST + c * 16,
             qH + ((size_t)(b * T_ + t0q + r) * NH_ + h) * HD_ + c * 8);
    }
    // KV stage 0 (128 keys)
    #pragma unroll
    for (int p = 0; p < 16; ++p) {
        int idx = tid + p * 256;                 // 0..4095
        int part = idx >> 11;                    // 0=K,1=V
        int r = (idx >> 4) & 127, c = idx & 15;
        const __half* src = part ? vH : kH;
        cp16(sb + QT + part * KVP2 + r * FST + c * 16,
             src + ((size_t)(b * T_ + r) * NKV_ + kvh) * HD_ + c * 8);
    }
    CP_COMMIT();
    CP_WAIT0();
    __syncthreads();

    uint32_t QF[8][4];
    #pragma unroll
    for (int ks = 0; ks < 8; ++ks) {
        uint32_t ra = sb + (wid * 16 + (lane & 15)) * FST
                    + ks * 32 + ((lane >> 4) << 4);
        ldsm_x4(QF[ks], ra);
    }

    float m0 = NEG_INF, m1 = NEG_INF, l0 = 0.f, l1 = 0.f;
    float O[16][4];
    #pragma unroll
    for (int nt = 0; nt < 16; ++nt)
        #pragma unroll
        for (int j = 0; j < 4; ++j) O[nt][j] = 0.f;

    const int row_a = t0q + wid * 16 + (lane >> 2);

    for (int jt = 0; jt <= itq; ++jt) {
        const int buf = jt & 1;
        if (jt > 0) { CP_WAIT0(); __syncthreads(); }
        if (jt + 1 <= itq) {
            const int t0n = (jt + 1) * 128;
            #pragma unroll
            for (int p = 0; p < 16; ++p) {
                int idx = tid + p * 256;
                int part = idx >> 11;
                int r = (idx >> 4) & 127, c = idx & 15;
                const __half* src = part ? vH : kH;
                cp16(sb + QT + (buf ^ 1) * STG2 + part * KVP2 + r * FST + c * 16,
                     src + ((size_t)(b * T_ + t0n + r) * NKV_ + kvh) * HD_ + c * 8);
            }
            CP_COMMIT();
        }

        const uint32_t base_k = sb + QT + buf * STG2;
        const uint32_t base_v = base_k + KVP2;
        const int t0k = jt * 128;

        // ---- S = Q K^T over 128 keys ----
        float S[16][4];
        #pragma unroll
        for (int nt = 0; nt < 16; ++nt)
            #pragma unroll
            for (int j = 0; j < 4; ++j) S[nt][j] = 0.f;

        #pragma unroll
        for (int ks = 0; ks < 8; ++ks) {
            #pragma unroll
            for (int ntp = 0; ntp < 8; ++ntp) {
                uint32_t bh[4];
                uint32_t rb = base_k
                            + (ntp * 16 + (lane & 7) + ((lane >> 4) << 3)) * FST
                            + ks * 32 + (((lane >> 3) & 1) << 4);
                ldsm_x4(bh, rb);
                mma_f16(S[2 * ntp],     QF[ks], bh);
                mma_f16(S[2 * ntp + 1], QF[ks], bh + 2);
            }
        }

        // ---- causal mask + row max ----
        const bool diag = (jt == itq);
        float ml0 = NEG_INF, ml1 = NEG_INF;
        #pragma unroll
        for (int nt = 0; nt < 16; ++nt) {
            int c = t0k + nt * 8 + 2 * (lane & 3);
            if (diag) {
                if (c     > row_a)     S[nt][0] = NEG_INF;
                if (c + 1 > row_a)     S[nt][1] = NEG_INF;
                if (c     > row_a + 8) S[nt][2] = NEG_INF;
                if (c + 1 > row_a + 8) S[nt][3] = NEG_INF;
            }
            ml0 = fmaxf(ml0, fmaxf(S[nt][0], S[nt][1]));
            ml1 = fmaxf(ml1, fmaxf(S[nt][2], S[nt][3]));
        }
        ml0 = fmaxf(ml0, __shfl_xor_sync(0xffffffffu, ml0, 1));
        ml0 = fmaxf(ml0, __shfl_xor_sync(0xffffffffu, ml0, 2));
        ml1 = fmaxf(ml1, __shfl_xor_sync(0xffffffffu, ml1, 1));
        ml1 = fmaxf(ml1, __shfl_xor_sync(0xffffffffu, ml1, 2));

        float mn0 = fmaxf(m0, ml0), mn1 = fmaxf(m1, ml1);
        float es0 = exp2f(m0 - mn0);
        float es1 = exp2f(m1 - mn1);
        m0 = mn0; m1 = mn1;
        #pragma unroll
        for (int nt = 0; nt < 16; ++nt) {
            O[nt][0] *= es0; O[nt][1] *= es0;
            O[nt][2] *= es1; O[nt][3] *= es1;
        }

        // ---- exp + PV in two 64-key halves (PH stays 16 regs) ----
        float sum0 = 0.f, sum1 = 0.f;
        #pragma unroll
        for (int half = 0; half < 2; ++half) {
            uint32_t PH[16];
            #pragma unroll
            for (int ntl = 0; ntl < 8; ++ntl) {
                int nt = half * 8 + ntl;
                float p0 = exp2f(S[nt][0] - mn0);
                float p1 = exp2f(S[nt][1] - mn0);
                float p2 = exp2f(S[nt][2] - mn1);
                float p3 = exp2f(S[nt][3] - mn1);
                sum0 += p0 + p1;  sum1 += p2 + p3;
                __half2 hA = __floats2half2_rn(p0, p1);
                __half2 hB = __floats2half2_rn(p2, p3);
                PH[2 * ntl]     = *(uint32_t*)&hA;
                PH[2 * ntl + 1] = *(uint32_t*)&hB;
            }
            #pragma unroll
            for (int kt = 0; kt < 4; ++kt) {
                uint32_t pa[4] = { PH[4*kt], PH[4*kt+1], PH[4*kt+2], PH[4*kt+3] };
                #pragma unroll
                for (int ntp = 0; ntp < 8; ++ntp) {
                    uint32_t bh[4];
                    uint32_t rv = base_v
                                + (half * 64 + kt * 16 + (lane & 7) + (lane & 8)) * FST
                                + ntp * 32 + ((lane >> 4) << 4);
                    ldsm_x4_t(bh, rv);
                    mma_f16(O[2 * ntp],     pa, bh);
                    mma_f16(O[2 * ntp + 1], pa, bh + 2);
                }
            }
        }
        sum0 += __shfl_xor_sync(0xffffffffu, sum0, 1);
        sum0 += __shfl_xor_sync(0xffffffffu, sum0, 2);
        sum1 += __shfl_xor_sync(0xffffffffu, sum1, 1);
        sum1 += __shfl_xor_sync(0xffffffffu, sum1, 2);
        l0 = l0 * es0 + sum0;
        l1 = l1 * es1 + sum1;
    }

    float inv0 = 1.f / l0, inv1 = 1.f / l1;
    #pragma unroll
    for (int nt = 0; nt < 16; ++nt) {
        int c = nt * 8 + 2 * (lane & 3);
        size_t baseA = ((size_t)(b * T_ + row_a) * NH_ + h) * HD_ + c;
        size_t baseB = ((size_t)(b * T_ + row_a + 8) * NH_ + h) * HD_ + c;
        __half2 uA = __floats2half2_rn(O[nt][0] * inv0, O[nt][1] * inv0);
        __half2 uB = __floats2half2_rn(O[nt][2] * inv1, O[nt][3] * inv1);
        *(uint32_t*)(y + baseA) = *(uint32_t*)&uA;
        *(uint32_t*)(y + baseB) = *(uint32_t*)&uB;
    }
}

// ---------------------------------------------------------------------------
extern "C" void kernel_launch(void* const* d_in, const int* in_sizes, int n_in,
                              void* d_out, int out_size)
{
    const float* x  = (const float*)d_in[0];
    const float* Wq = (const float*)d_in[1];
    const float* Wk = (const float*)d_in[2];
    const float* Wv = (const float*)d_in[3];
    const float* Wp = (const float*)d_in[4];
    const float* qg = (const float*)d_in[5];
    float* out = (float*)d_out;

    __half *xH, *wqH, *wkH, *wvH, *wpH, *qh16, *kh16, *vh16, *yH;
    cudaGetSymbolAddress((void**)&xH,  g_xH);
    cudaGetSymbolAddress((void**)&wqH, g_wqH);
    cudaGetSymbolAddress((void**)&wkH, g_wkH);
    cudaGetSymbolAddress((void**)&wvH, g_wvH);
    cudaGetSymbolAddress((void**)&wpH, g_wpH);
    cudaGetSymbolAddress((void**)&qh16, g_qH);
    cudaGetSymbolAddress((void**)&kh16, g_kH);
    cudaGetSymbolAddress((void**)&vh16, g_vH);
    cudaGetSymbolAddress((void**)&yH,  g_yH);

    cudaFuncSetAttribute(gemm_qkv, cudaFuncAttributeMaxDynamicSharedMemorySize, HSMEM);
    cudaFuncSetAttribute(gemm_out, cudaFuncAttributeMaxDynamicSharedMemorySize, HSMEM);
    cudaFuncSetAttribute(flash_mma, cudaFuncAttributeMaxDynamicSharedMemorySize, FSMEM2);

    // (0) RoPE tables, (1) operand prep
    rope_table_kernel<<<(T_ * 64 + 255) / 256, 256>>>();
    split_all_kernel<<<(SPLIT_TOT + 1023) / 1024, 256>>>(x, Wq, Wk, Wv, Wp);

    // (2) fused Q+K+V projection with RMSNorm+RoPE epilogue -> fp16
    gemm_qkv<<<dim3(24, (B_ * T_) / 128), 512, HSMEM>>>(
        xH, wqH, wkH, wvH, qg, qh16, kh16, vh16);

    // (3) flash attention (128-key KV tiles) -> y fp16
    flash_mma<<<dim3(T_ / 128, NH_, B_), 256, FSMEM2>>>(qh16, kh16, vh16, yH);

    // (4) out projection -> fp32 out
    gemm_out<<<dim3(DIM_ / 128, (B_ * T_) / 128), 512, HSMEM>>>(
        yH, wpH, out, DIM_, DIM_);
}

// round 15
// speedup vs baseline: 1.1930x; 1.0011x over previous
#include <cuda_runtime.h>
#include <cuda_bf16.h>
#include <cuda_fp16.h>
#include <math.h>
#include <stdint.h>

#define B_    2
#define T_    2048
#define DIM_  2048
#define NH_   16
#define NKV_  4
#define HD_   128
#define KD_   512
#define GQ_   (NH_ / NKV_)
#define EPS_  1.1920928955078125e-07f

// ---------------- scratch ----------------------------------------------------
__device__ float g_cos[T_ * (HD_ / 2)];
__device__ float g_sin[T_ * (HD_ / 2)];
__device__ __half g_xH[(size_t)B_ * T_ * DIM_];
__device__ __half g_wqH[(size_t)DIM_ * DIM_];
__device__ __half g_wkH[(size_t)KD_ * DIM_];
__device__ __half g_wvH[(size_t)KD_ * DIM_];
__device__ __half g_wpH[(size_t)DIM_ * DIM_];
__device__ __half g_qH[(size_t)B_ * T_ * DIM_];
__device__ __half g_kH[(size_t)B_ * T_ * KD_];
__device__ __half g_vH[(size_t)B_ * T_ * KD_];
__device__ __half g_yH[(size_t)B_ * T_ * DIM_];

// ---------------- helpers ----------------------------------------------------
__device__ __forceinline__ uint32_t smem_u32(const void* p) {
    uint32_t a;
    asm("{ .reg .u64 t; cvta.to.shared.u64 t, %1; cvt.u32.u64 %0, t; }"
        : "=r"(a) : "l"(p));
    return a;
}
__device__ __forceinline__ float ex2(float x) {
    float r;
    asm("ex2.approx.ftz.f32 %0, %1;" : "=f"(r) : "f"(x));
    return r;
}
__device__ __forceinline__ float rsqrt_a(float x) {
    float r;
    asm("rsqrt.approx.f32 %0, %1;" : "=f"(r) : "f"(x));
    return r;
}
__device__ __forceinline__ void mma_f16(float* d, const uint32_t* a, const uint32_t* b) {
    asm volatile("mma.sync.aligned.m16n8k16.row.col.f32.f16.f16.f32 "
        "{%0,%1,%2,%3}, {%4,%5,%6,%7}, {%8,%9}, {%0,%1,%2,%3};"
        : "+f"(d[0]), "+f"(d[1]), "+f"(d[2]), "+f"(d[3])
        : "r"(a[0]), "r"(a[1]), "r"(a[2]), "r"(a[3]), "r"(b[0]), "r"(b[1]));
}
__device__ __forceinline__ void ldsm_x4(uint32_t* r, uint32_t addr) {
    asm volatile("ldmatrix.sync.aligned.m8n8.x4.shared.b16 {%0,%1,%2,%3}, [%4];"
        : "=r"(r[0]), "=r"(r[1]), "=r"(r[2]), "=r"(r[3]) : "r"(addr));
}
__device__ __forceinline__ void ldsm_x4_t(uint32_t* r, uint32_t addr) {
    asm volatile("ldmatrix.sync.aligned.m8n8.x4.trans.shared.b16 {%0,%1,%2,%3}, [%4];"
        : "=r"(r[0]), "=r"(r[1]), "=r"(r[2]), "=r"(r[3]) : "r"(addr));
}
__device__ __forceinline__ void cp16(uint32_t dst, const void* src) {
    asm volatile("cp.async.cg.shared.global [%0], [%1], 16;" :: "r"(dst), "l"(src));
}
#define CP_COMMIT() asm volatile("cp.async.commit_group;" ::: "memory")
#define CP_WAIT0()  asm volatile("cp.async.wait_group 0;" ::: "memory")
#define CP_WAIT2()  asm volatile("cp.async.wait_group 2;" ::: "memory")

__device__ __forceinline__ uint2 tohalf4(float4 f) {
    __half2 h0 = __floats2half2_rn(f.x, f.y);
    __half2 h1 = __floats2half2_rn(f.z, f.w);
    return make_uint2(*(uint32_t*)&h0, *(uint32_t*)&h1);
}
#define NEG_INF __int_as_float(0xff800000)

// ---------------- RoPE tables ------------------------------------------------
__global__ void rope_table_kernel() {
    int idx = blockIdx.x * blockDim.x + threadIdx.x;
    if (idx >= T_ * (HD_ / 2)) return;
    int t = idx >> 6;
    int i = idx & 63;
    double base = 10000.0;
    if (T_ > 1024)
        base = 10000.0 * pow((double)T_ / 1024.0, (double)HD_ / (double)(HD_ - 2));
    double f = pow(base, -((double)(2 * i)) / (double)HD_);
    double a = (double)t * f;
    g_cos[idx] = (float)cos(a);
    g_sin[idx] = (float)sin(a);
}

// ---------------- operand prep: fp32 -> fp16, 4-way ILP ------------------------
#define S_X   (B_ * T_ * DIM_ / 4)
#define S_WQ  (DIM_ * DIM_ / 4)
#define S_WK  (KD_ * DIM_ / 4)
#define SPLIT_TOT (S_X + S_WQ + S_WK + S_WK + S_WQ)

__device__ __forceinline__ void split_one(int i,
    const float* x, const float* Wq, const float* Wk,
    const float* Wv, const float* Wp)
{
    if (i < S_X)  { ((uint2*)g_xH)[i]  = tohalf4(((const float4*)x)[i]);  return; }
    i -= S_X;
    if (i < S_WQ) { ((uint2*)g_wqH)[i] = tohalf4(((const float4*)Wq)[i]); return; }
    i -= S_WQ;
    if (i < S_WK) { ((uint2*)g_wkH)[i] = tohalf4(((const float4*)Wk)[i]); return; }
    i -= S_WK;
    if (i < S_WK) { ((uint2*)g_wvH)[i] = tohalf4(((const float4*)Wv)[i]); return; }
    i -= S_WK;
    ((uint2*)g_wpH)[i] = tohalf4(((const float4*)Wp)[i]);
}

__global__ void split_all_kernel(const float* __restrict__ x,
                                 const float* __restrict__ Wq,
                                 const float* __restrict__ Wk,
                                 const float* __restrict__ Wv,
                                 const float* __restrict__ Wp)
{
    int base = blockIdx.x * 1024 + threadIdx.x;
    #pragma unroll
    for (int k = 0; k < 4; ++k) {
        int i = base + k * 256;
        if (i < SPLIT_TOT) split_one(i, x, Wq, Wk, Wv, Wp);
    }
}

// ---------------- 1-term fp16 GEMM body (512 thr, 4-stage) ---------------------
#define HST     144
#define HPART   (128 * HST)
#define HSTAGE  (2 * HPART)
#define HSMEM   (4 * HSTAGE)

template<int KIND>
__device__ __forceinline__ void gemm1_body(
    const __half* __restrict__ A, const __half* __restrict__ W,
    float* __restrict__ C, __half* __restrict__ Ch,
    int N, int K, int bm, int bn, float post_mul)
{
    extern __shared__ char sm[];
    const uint32_t sb = smem_u32(sm);
    const int tid = threadIdx.x, wid = tid >> 5, lane = tid & 31;
    const int wm = wid & 3, wn = wid >> 2;

    float acc[2][4][4];
    #pragma unroll
    for (int i = 0; i < 2; ++i)
        #pragma unroll
        for (int j = 0; j < 4; ++j)
            #pragma unroll
            for (int q = 0; q < 4; ++q) acc[i][j][q] = 0.f;

    const int niter = K / 64;

    auto load_stage = [&](int it, int buf) {
        const int k0 = it * 64;
        const uint32_t s = sb + buf * HSTAGE;
        #pragma unroll
        for (int p = 0; p < 4; ++p) {
            int idx  = tid + p * 512;
            int part = idx >> 10;
            int r    = (idx >> 3) & 127;
            int c    = idx & 7;
            const __half* src = part ? W : A;
            int rowg = (part ? bn : bm) + r;
            cp16(s + part * HPART + r * HST + c * 16,
                 src + (size_t)rowg * K + k0 + c * 8);
        }
    };

    load_stage(0, 0); CP_COMMIT();
    load_stage(1, 1); CP_COMMIT();
    load_stage(2, 2); CP_COMMIT();

    for (int it = 0; it < niter; ++it) {
        const int buf = it & 3;
        CP_WAIT2();
        __syncthreads();
        if (it + 3 < niter) { load_stage(it + 3, (it + 3) & 3); CP_COMMIT(); }

        const uint32_t sbuf = sb + buf * HSTAGE;
        #pragma unroll
        for (int ks = 0; ks < 4; ++ks) {
            uint32_t a[2][4], b[2][4];
            #pragma unroll
            for (int mt = 0; mt < 2; ++mt) {
                uint32_t ra = sbuf + (wm * 32 + mt * 16 + (lane & 15)) * HST
                            + ks * 32 + ((lane >> 4) << 4);
                ldsm_x4(a[mt], ra);
            }
            #pragma unroll
            for (int pr = 0; pr < 2; ++pr) {
                uint32_t rb = sbuf + HPART
                            + (wn * 32 + pr * 16 + (lane & 7) + ((lane >> 4) << 3)) * HST
                            + ks * 32 + (((lane >> 3) & 1) << 4);
                ldsm_x4(b[pr], rb);
            }
            #pragma unroll
            for (int mt = 0; mt < 2; ++mt)
                #pragma unroll
                for (int nt = 0; nt < 4; ++nt)
                    mma_f16(acc[mt][nt], a[mt], b[nt >> 1] + (nt & 1) * 2);
        }
        __syncthreads();
    }

    if (KIND == 0 || KIND == 1) {
        #pragma unroll
        for (int mt = 0; mt < 2; ++mt)
            #pragma unroll
            for (int nt = 0; nt < 4; ++nt) {
                int row = bm + wm * 32 + mt * 16 + (lane >> 2);
                int col = bn + wn * 32 + nt * 8 + 2 * (lane & 3);
                if (KIND == 1) {
                    __half2 u0 = __floats2half2_rn(acc[mt][nt][0], acc[mt][nt][1]);
                    __half2 u1 = __floats2half2_rn(acc[mt][nt][2], acc[mt][nt][3]);
                    *(uint32_t*)(Ch + (size_t)row * N + col)       = *(uint32_t*)&u0;
                    *(uint32_t*)(Ch + (size_t)(row + 8) * N + col) = *(uint32_t*)&u1;
                } else {
                    *(float2*)(C + (size_t)row * N + col) =
                        make_float2(acc[mt][nt][0], acc[mt][nt][1]);
                    *(float2*)(C + (size_t)(row + 8) * N + col) =
                        make_float2(acc[mt][nt][2], acc[mt][nt][3]);
                }
            }
        return;
    }

    // ---- KIND == 2: fused RMSNorm + RoPE epilogue (tile = one head) ----
    float* ssq_sm = (float*)sm;
    float* tile   = (float*)(sm + 2048);           // [128][132]

    float ssq[2][2];
    #pragma unroll
    for (int mt = 0; mt < 2; ++mt)
        #pragma unroll
        for (int hf = 0; hf < 2; ++hf) {
            float s = 0.f;
            #pragma unroll
            for (int nt = 0; nt < 4; ++nt) {
                float v0 = acc[mt][nt][hf * 2 + 0];
                float v1 = acc[mt][nt][hf * 2 + 1];
                s += v0 * v0 + v1 * v1;
            }
            s += __shfl_xor_sync(0xffffffffu, s, 1);
            s += __shfl_xor_sync(0xffffffffu, s, 2);
            ssq[mt][hf] = s;
        }
    if ((lane & 3) == 0) {
        #pragma unroll
        for (int mt = 0; mt < 2; ++mt)
            #pragma unroll
            for (int hf = 0; hf < 2; ++hf) {
                int row = wm * 32 + mt * 16 + hf * 8 + (lane >> 2);
                ssq_sm[row * 4 + wn] = ssq[mt][hf];
            }
    }
    __syncthreads();

    #pragma unroll
    for (int mt = 0; mt < 2; ++mt)
        #pragma unroll
        for (int hf = 0; hf < 2; ++hf) {
            int row = wm * 32 + mt * 16 + hf * 8 + (lane >> 2);
            float tot = ssq_sm[row * 4 + 0] + ssq_sm[row * 4 + 1]
                      + ssq_sm[row * 4 + 2] + ssq_sm[row * 4 + 3];
            float rr = rsqrtf(tot * (1.f / HD_) + EPS_) * post_mul;
            #pragma unroll
            for (int nt = 0; nt < 4; ++nt) {
                int col = wn * 32 + nt * 8 + 2 * (lane & 3);
                tile[row * 132 + col]     = acc[mt][nt][hf * 2 + 0] * rr;
                tile[row * 132 + col + 1] = acc[mt][nt][hf * 2 + 1] * rr;
            }
        }
    __syncthreads();

    #pragma unroll
    for (int mt = 0; mt < 2; ++mt)
        #pragma unroll
        for (int hf = 0; hf < 2; ++hf) {
            int row = wm * 32 + mt * 16 + hf * 8 + (lane >> 2);
            int t   = (bm + row) & (T_ - 1);
            #pragma unroll
            for (int nt = 0; nt < 4; ++nt) {
                int col = wn * 32 + nt * 8 + 2 * (lane & 3);
                float o[2];
                #pragma unroll
                for (int e = 0; e < 2; ++e) {
                    int c0 = col + e;
                    float own = tile[row * 132 + c0];
                    float par = tile[row * 132 + (c0 ^ 64)];
                    int i = c0 & 63;
                    float cs = g_cos[t * 64 + i];
                    float sn = g_sin[t * 64 + i];
                    o[e] = (c0 < 64) ? (own * cs + par * sn)
                                     : (own * cs - par * sn);
                }
                __half2 u = __floats2half2_rn(o[0], o[1]);
                *(uint32_t*)(Ch + (size_t)(bm + row) * N + bn + col) = *(uint32_t*)&u;
            }
        }
}

__global__ void __launch_bounds__(512, 1) gemm_qkv(
    const __half* __restrict__ xH,
    const __half* __restrict__ wq, const __half* __restrict__ wk,
    const __half* __restrict__ wv, const float* __restrict__ qg,
    __half* __restrict__ qO, __half* __restrict__ kO, __half* __restrict__ vO)
{
    const int bx = blockIdx.x;
    const float QMUL = 0.08838834764831845f * 1.44269504088896340736f;
    if (bx < 16) {
        float pm = qg[bx] * QMUL;
        gemm1_body<2>(xH, wq, nullptr, qO, DIM_, DIM_,
                      blockIdx.y * 128, bx * 128, pm);
    } else if (bx < 20) {
        gemm1_body<2>(xH, wk, nullptr, kO, KD_, DIM_,
                      blockIdx.y * 128, (bx - 16) * 128, 1.0f);
    } else {
        gemm1_body<1>(xH, wv, nullptr, vO, KD_, DIM_,
                      blockIdx.y * 128, (bx - 20) * 128, 1.0f);
    }
}

__global__ void __launch_bounds__(512, 1) gemm_out(
    const __half* __restrict__ A, const __half* __restrict__ W,
    float* __restrict__ C, int N, int K)
{
    gemm1_body<0>(A, W, C, nullptr, N, K, blockIdx.y * 128, blockIdx.x * 128, 1.0f);
}

// ---------------- flash attention: fp16, 128-key KV tiles ----------------------
#define FST     272
#define QT      (128 * FST)
#define KVP2    (128 * FST)
#define STG2    (2 * KVP2)
#define FSMEM2  (QT + 2 * STG2)      // 174080

__global__ void __launch_bounds__(256, 1) flash_mma(
    const __half* __restrict__ qH, const __half* __restrict__ kH,
    const __half* __restrict__ vH, __half* __restrict__ y)
{
    extern __shared__ char sm[];
    const uint32_t sb = smem_u32(sm);
    const int tid = threadIdx.x, wid = tid >> 5, lane = tid & 31;
    const int itq = (gridDim.x - 1) - blockIdx.x;
    const int h = blockIdx.y, b = blockIdx.z;
    const int kvh = h / GQ_;
    const int t0q = itq * 128;

    #pragma unroll
    for (int p = 0; p < 8; ++p) {
        int idx = tid + p * 256;
        int r = (idx >> 4) & 127, c = idx & 15;
        cp16(sb + r * FST + c * 16,
             qH + ((size_t)(b * T_ + t0q + r) * NH_ + h) * HD_ + c * 8);
    }
    #pragma unroll
    for (int p = 0; p < 16; ++p) {
        int idx = tid + p * 256;
        int part = idx >> 11;
        int r = (idx >> 4) & 127, c = idx & 15;
        const __half* src = part ? vH : kH;
        cp16(sb + QT + part * KVP2 + r * FST + c * 16,
             src + ((size_t)(b * T_ + r) * NKV_ + kvh) * HD_ + c * 8);
    }
    CP_COMMIT();
    CP_WAIT0();
    __syncthreads();

    uint32_t QF[8][4];
    #pragma unroll
    for (int ks = 0; ks < 8; ++ks) {
        uint32_t ra = sb + (wid * 16 + (lane & 15)) * FST
                    + ks * 32 + ((lane >> 4) << 4);
        ldsm_x4(QF[ks], ra);
    }

    float m0 = NEG_INF, m1 = NEG_INF, l0 = 0.f, l1 = 0.f;
    float O[16][4];
    #pragma unroll
    for (int nt = 0; nt < 16; ++nt)
        #pragma unroll
        for (int j = 0; j < 4; ++j) O[nt][j] = 0.f;

    const int row_a = t0q + wid * 16 + (lane >> 2);

    for (int jt = 0; jt <= itq; ++jt) {
        const int buf = jt & 1;
        if (jt > 0) { CP_WAIT0(); __syncthreads(); }
        if (jt + 1 <= itq) {
            const int t0n = (jt + 1) * 128;
            #pragma unroll
            for (int p = 0; p < 16; ++p) {
                int idx = tid + p * 256;
                int part = idx >> 11;
                int r = (idx >> 4) & 127, c = idx & 15;
                const __half* src = part ? vH : kH;
                cp16(sb + QT + (buf ^ 1) * STG2 + part * KVP2 + r * FST + c * 16,
                     src + ((size_t)(b * T_ + t0n + r) * NKV_ + kvh) * HD_ + c * 8);
            }
            CP_COMMIT();
        }

        const uint32_t base_k = sb + QT + buf * STG2;
        const uint32_t base_v = base_k + KVP2;
        const int t0k = jt * 128;

        float S[16][4];
        #pragma unroll
        for (int nt = 0; nt < 16; ++nt)
            #pragma unroll
            for (int j = 0; j < 4; ++j) S[nt][j] = 0.f;

        #pragma unroll
        for (int ks = 0; ks < 8; ++ks) {
            #pragma unroll
            for (int ntp = 0; ntp < 8; ++ntp) {
                uint32_t bh[4];
                uint32_t rb = base_k
                            + (ntp * 16 + (lane & 7) + ((lane >> 4) << 3)) * FST
                            + ks * 32 + (((lane >> 3) & 1) << 4);
                ldsm_x4(bh, rb);
                mma_f16(S[2 * ntp],     QF[ks], bh);
                mma_f16(S[2 * ntp + 1], QF[ks], bh + 2);
            }
        }

        const bool diag = (jt == itq);
        float ml0 = NEG_INF, ml1 = NEG_INF;
        #pragma unroll
        for (int nt = 0; nt < 16; ++nt) {
            int c = t0k + nt * 8 + 2 * (lane & 3);
            if (diag) {
                if (c     > row_a)     S[nt][0] = NEG_INF;
                if (c + 1 > row_a)     S[nt][1] = NEG_INF;
                if (c     > row_a + 8) S[nt][2] = NEG_INF;
                if (c + 1 > row_a + 8) S[nt][3] = NEG_INF;
            }
            ml0 = fmaxf(ml0, fmaxf(S[nt][0], S[nt][1]));
            ml1 = fmaxf(ml1, fmaxf(S[nt][2], S[nt][3]));
        }
        ml0 = fmaxf(ml0, __shfl_xor_sync(0xffffffffu, ml0, 1));
        ml0 = fmaxf(ml0, __shfl_xor_sync(0xffffffffu, ml0, 2));
        ml1 = fmaxf(ml1, __shfl_xor_sync(0xffffffffu, ml1, 1));
        ml1 = fmaxf(ml1, __shfl_xor_sync(0xffffffffu, ml1, 2));

        float mn0 = fmaxf(m0, ml0), mn1 = fmaxf(m1, ml1);
        float es0 = ex2(m0 - mn0);
        float es1 = ex2(m1 - mn1);
        m0 = mn0; m1 = mn1;
        #pragma unroll
        for (int nt = 0; nt < 16; ++nt) {
            O[nt][0] *= es0; O[nt][1] *= es0;
            O[nt][2] *= es1; O[nt][3] *= es1;
        }

        float sum0 = 0.f, sum1 = 0.f;
        #pragma unroll
        for (int half = 0; half < 2; ++half) {
            uint32_t PH[16];
            #pragma unroll
            for (int ntl = 0; ntl < 8; ++ntl) {
                int nt = half * 8 + ntl;
                float p0 = ex2(S[nt][0] - mn0);
                float p1 = ex2(S[nt][1] - mn0);
                float p2 = ex2(S[nt][2] - mn1);
                float p3 = ex2(S[nt][3] - mn1);
                sum0 += p0 + p1;  sum1 += p2 + p3;
                __half2 hA = __floats2half2_rn(p0, p1);
                __half2 hB = __floats2half2_rn(p2, p3);
                PH[2 * ntl]     = *(uint32_t*)&hA;
                PH[2 * ntl + 1] = *(uint32_t*)&hB;
            }
            #pragma unroll
            for (int kt = 0; kt < 4; ++kt) {
                uint32_t pa[4] = { PH[4*kt], PH[4*kt+1], PH[4*kt+2], PH[4*kt+3] };
                #pragma unroll
                for (int ntp = 0; ntp < 8; ++ntp) {
                    uint32_t bh[4];
                    uint32_t rv = base_v
                                + (half * 64 + kt * 16 + (lane & 7) + (lane & 8)) * FST
                                + ntp * 32 + ((lane >> 4) << 4);
                    ldsm_x4_t(bh, rv);
                    mma_f16(O[2 * ntp],     pa, bh);
                    mma_f16(O[2 * ntp + 1], pa, bh + 2);
                }
            }
        }
        sum0 += __shfl_xor_sync(0xffffffffu, sum0, 1);
        sum0 += __shfl_xor_sync(0xffffffffu, sum0, 2);
        sum1 += __shfl_xor_sync(0xffffffffu, sum1, 1);
        sum1 += __shfl_xor_sync(0xffffffffu, sum1, 2);
        l0 = l0 * es0 + sum0;
        l1 = l1 * es1 + sum1;
    }

    float inv0 = 1.f / l0, inv1 = 1.f / l1;
    #pragma unroll
    for (int nt = 0; nt < 16; ++nt) {
        int c = nt * 8 + 2 * (lane & 3);
        size_t baseA = ((size_t)(b * T_ + row_a) * NH_ + h) * HD_ + c;
        size_t baseB = ((size_t)(b * T_ + row_a + 8) * NH_ + h) * HD_ + c;
        __half2 uA = __floats2half2_rn(O[nt][0] * inv0, O[nt][1] * inv0);
        __half2 uB = __floats2half2_rn(O[nt][2] * inv1, O[nt][3] * inv1);
        *(uint32_t*)(y + baseA) = *(uint32_t*)&uA;
        *(uint32_t*)(y + baseB) = *(uint32_t*)&uB;
    }
}

// ---------------------------------------------------------------------------
extern "C" void kernel_launch(void* const* d_in, const int* in_sizes, int n_in,
                              void* d_out, int out_size)
{
    const float* x  = (const float*)d_in[0];
    const float* Wq = (const float*)d_in[1];
    const float* Wk = (const float*)d_in[2];
    const float* Wv = (const float*)d_in[3];
    const float* Wp = (const float*)d_in[4];
    const float* qg = (const float*)d_in[5];
    float* out = (float*)d_out;

    __half *xH, *wqH, *wkH, *wvH, *wpH, *qh16, *kh16, *vh16, *yH;
    cudaGetSymbolAddress((void**)&xH,  g_xH);
    cudaGetSymbolAddress((void**)&wqH, g_wqH);
    cudaGetSymbolAddress((void**)&wkH, g_wkH);
    cudaGetSymbolAddress((void**)&wvH, g_wvH);
    cudaGetSymbolAddress((void**)&wpH, g_wpH);
    cudaGetSymbolAddress((void**)&qh16, g_qH);
    cudaGetSymbolAddress((void**)&kh16, g_kH);
    cudaGetSymbolAddress((void**)&vh16, g_vH);
    cudaGetSymbolAddress((void**)&yH,  g_yH);

    cudaFuncSetAttribute(gemm_qkv, cudaFuncAttributeMaxDynamicSharedMemorySize, HSMEM);
    cudaFuncSetAttribute(gemm_out, cudaFuncAttributeMaxDynamicSharedMemorySize, HSMEM);
    cudaFuncSetAttribute(flash_mma, cudaFuncAttributeMaxDynamicSharedMemorySize, FSMEM2);

    rope_table_kernel<<<(T_ * 64 + 255) / 256, 256>>>();
    split_all_kernel<<<(SPLIT_TOT + 1023) / 1024, 256>>>(x, Wq, Wk, Wv, Wp);

    gemm_qkv<<<dim3(24, (B_ * T_) / 128), 512, HSMEM>>>(
        xH, wqH, wkH, wvH, qg, qh16, kh16, vh16);

    flash_mma<<<dim3(T_ / 128, NH_, B_), 256, FSMEM2>>>(qh16, kh16, vh16, yH);

    gemm_out<<<dim3(DIM_ / 128, (B_ * T_) / 128), 512, HSMEM>>>(
        yH, wpH, out, DIM_, DIM_);
}